// round 14
// baseline (speedup 1.0000x reference)
#include <cuda_runtime.h>
#include <cuda_bf16.h>
#include <math.h>
#include <stdint.h>

// ---------------- problem constants ----------------
constexpr int B_   = 16;
constexpr int T_   = 256;
constexpr int CH_  = 16;
constexpr int CIN_ = 64;
constexpr int D_   = 512;
constexpr int H_   = 8;
constexpr int E_   = 64;
constexpr int NL_  = 2;
constexpr int M_   = 64;
constexpr int L_   = T_ + 1; // 257
constexpr int LP_  = 264;
constexpr int BE_  = B_ * CH_;      // 256
constexpr int MR   = BE_ * L_;      // 65792 = 514*128
constexpr int R_   = BE_ * D_;      // 131072
constexpr int K3   = 3 * CIN_;      // 192
constexpr int STGS = 136;           // staged-epilogue smem row stride (floats)

// ---------------- scratch ----------------
__device__ float g_h   [(size_t)BE_ * L_ * D_];
__device__ float g_q   [(size_t)BE_ * L_ * D_];
__device__ float g_t   [(size_t)BE_ * L_ * D_];   // Ainv alias
__device__ float g_xq  [(size_t)BE_ * D_ * L_];
__device__ float g_xqp [(size_t)BE_ * D_ * LP_];
__device__ float g_W2t [(size_t)D_ * K3];
__device__ float g_cs  [128 * LP_];
__device__ float g_Binv[L_ * 2 * M_];
__device__ float g_z  [BE_ * D_];
__device__ float g_z2 [B_ * D_];
__device__ __nv_bfloat16 g_A2a[(size_t)MR * 3 * D_];  // split activations (ping)
__device__ __nv_bfloat16 g_A2b[(size_t)MR * 3 * D_];  // split activations (pong)
__device__ __nv_bfloat16 g_B2 [(size_t)D_ * 3 * D_];  // split weights [hi|hi|lo]

// ================= helpers =================
__device__ __forceinline__ uint32_t smem_u32(const void* p) {
    uint32_t a;
    asm("{ .reg .u64 t; cvta.to.shared.u64 t, %1; cvt.u32.u64 %0, t; }" : "=r"(a) : "l"(p));
    return a;
}
__device__ __forceinline__ void ldsm4(uint32_t& r0, uint32_t& r1, uint32_t& r2, uint32_t& r3,
                                      uint32_t a) {
    asm volatile("ldmatrix.sync.aligned.m8n8.x4.shared.b16 {%0,%1,%2,%3}, [%4];"
                 : "=r"(r0), "=r"(r1), "=r"(r2), "=r"(r3) : "r"(a));
}
__device__ __forceinline__ void mma_bf16(float& d0, float& d1, float& d2, float& d3,
                                         uint32_t a0, uint32_t a1, uint32_t a2, uint32_t a3,
                                         uint32_t b0, uint32_t b1) {
    asm volatile("mma.sync.aligned.m16n8k16.row.col.f32.bf16.bf16.f32 "
                 "{%0,%1,%2,%3}, {%4,%5,%6,%7}, {%8,%9}, {%0,%1,%2,%3};"
                 : "+f"(d0), "+f"(d1), "+f"(d2), "+f"(d3)
                 : "r"(a0), "r"(a1), "r"(a2), "r"(a3), "r"(b0), "r"(b1));
}
__device__ __forceinline__ void cp16(uint32_t dst, const void* src) {
    asm volatile("cp.async.cg.shared.global [%0], [%1], 16;"
                 :: "r"(dst), "l"(__cvta_generic_to_global(src)) : "memory");
}
// A-side split layout [hi | lo | hi]
__device__ __forceinline__ void write_split(__nv_bfloat16* o, int K, float v) {
    const __nv_bfloat16 hi = __float2bfloat16_rn(v);
    const __nv_bfloat16 lo = __float2bfloat16_rn(v - __bfloat162float(hi));
    o[0] = hi; o[K] = lo; o[2 * K] = hi;
}
__device__ __forceinline__ float gelu1(float v) {
    return 0.5f * v * (1.f + erff(v * 0.70710678118654752f));
}

// ========== standalone A-split: fp32 [rows,K] -> bf16 [rows,3K] = [hi|lo|hi] ==========
__global__ void k_split(const float* __restrict__ A, __nv_bfloat16* __restrict__ out,
                        int K, int total4) {
    const int idx = blockIdx.x * blockDim.x + threadIdx.x;
    if (idx >= total4) return;
    const int Kq = K >> 2;
    const int row = idx / Kq;
    const int c   = (idx - row * Kq) << 2;
    const float4 v = *reinterpret_cast<const float4*>(A + (size_t)row * K + c);
    __nv_bfloat16 hi[4], lo[4];
    const float vv[4] = {v.x, v.y, v.z, v.w};
    #pragma unroll
    for (int j = 0; j < 4; ++j) {
        hi[j] = __float2bfloat16_rn(vv[j]);
        lo[j] = __float2bfloat16_rn(vv[j] - __bfloat162float(hi[j]));
    }
    __nv_bfloat16* o = out + (size_t)row * (3 * K);
    const uint2 hv = *reinterpret_cast<uint2*>(hi);
    const uint2 lv = *reinterpret_cast<uint2*>(lo);
    *reinterpret_cast<uint2*>(o + c)         = hv;
    *reinterpret_cast<uint2*>(o + K + c)     = lv;
    *reinterpret_cast<uint2*>(o + 2 * K + c) = hv;
}

// ========== weight split: [hi|hi|lo] ==========
__global__ void k_splitW(const float* __restrict__ A, __nv_bfloat16* __restrict__ out,
                         int K, int total4) {
    const int idx = blockIdx.x * blockDim.x + threadIdx.x;
    if (idx >= total4) return;
    const int Kq = K >> 2;
    const int row = idx / Kq;
    const int c   = (idx - row * Kq) << 2;
    const float4 v = *reinterpret_cast<const float4*>(A + (size_t)row * K + c);
    __nv_bfloat16 hi[4], lo[4];
    const float vv[4] = {v.x, v.y, v.z, v.w};
    #pragma unroll
    for (int j = 0; j < 4; ++j) {
        hi[j] = __float2bfloat16_rn(vv[j]);
        lo[j] = __float2bfloat16_rn(vv[j] - __bfloat162float(hi[j]));
    }
    __nv_bfloat16* o = out + (size_t)row * (3 * K);
    const uint2 hv = *reinterpret_cast<uint2*>(hi);
    const uint2 lv = *reinterpret_cast<uint2*>(lo);
    *reinterpret_cast<uint2*>(o + c)         = hv;
    *reinterpret_cast<uint2*>(o + K + c)     = hv;
    *reinterpret_cast<uint2*>(o + 2 * K + c) = lv;
}

// ================= bf16 mma.sync GEMM: C[M,512] = A2[M,K2] @ B2[512,K2]^T ==============
// CTA tile 128x256 (grid.x == 2), 8 warps, warp tile 64x64, 2-stage cp.async (110,592 B).
// mode 0: +bias ; 1: +bias+res ; 2: gelu(+bias)
// sOut != nullptr: emit [hi|lo|hi] split (row stride 1536) via smem-staged coalesced writes.
constexpr int STAGE_BYTES = 384 * 144;           // A 128 rows + B 256 rows, 144B each
constexpr int SMEM_MMA    = 2 * STAGE_BYTES;     // 110592

__global__ __launch_bounds__(256, 1)
void k_mma(const __nv_bfloat16* __restrict__ A2, const __nv_bfloat16* __restrict__ B2,
           float* __restrict__ C, const float* __restrict__ bias,
           const float* __restrict__ res, int K2, int mode,
           __nv_bfloat16* __restrict__ sOut) {
    extern __shared__ char smem[];
    const uint32_t sb = smem_u32(smem);
    const int tid = threadIdx.x;
    const int wid = tid >> 5, lane = tid & 31;
    const int mw = (wid & 1) * 64;     // warp m-offset in 128
    const int nw = (wid >> 1) * 64;    // warp n-offset in 256
    const int m0 = blockIdx.y * 128;
    const int n0 = blockIdx.x * 256;

    float acc[4][8][4] = {};   // [m-tile16][n-tile8][d]
    const int nch = K2 >> 6;

    #define LOAD_STAGE(c, s) do {                                                   \
        const uint32_t base = sb + (s) * STAGE_BYTES;                               \
        _Pragma("unroll")                                                           \
        for (int i = 0; i < 12; ++i) {                                              \
            const int idx = i * 256 + tid;          /* 0..3071 */                   \
            const int r = idx >> 3, sg = idx & 7;                                   \
            const __nv_bfloat16* src = (r < 128)                                    \
                ? A2 + (size_t)(m0 + r) * K2 + (c) * 64 + sg * 8                    \
                : B2 + (size_t)(n0 + r - 128) * K2 + (c) * 64 + sg * 8;             \
            cp16(base + r * 144 + sg * 16, src);                                    \
        }                                                                           \
        asm volatile("cp.async.commit_group;" ::: "memory");                        \
    } while (0)

    LOAD_STAGE(0, 0);

    const int a_row = mw + (lane & 15);
    const int a_kof = (lane >> 4) * 8;
    const int b_row = nw + ((lane >> 4) << 3) + (lane & 7);
    const int b_kof = ((lane >> 3) & 1) * 8;

    for (int c = 0; c < nch; ++c) {
        asm volatile("cp.async.wait_group 0;" ::: "memory");
        __syncthreads();
        if (c + 1 < nch) LOAD_STAGE(c + 1, (c + 1) & 1);

        const uint32_t aB = sb + (c & 1) * STAGE_BYTES;
        const uint32_t bB = aB + 128 * 144;

        #pragma unroll
        for (int ks = 0; ks < 4; ++ks) {
            uint32_t a[4][4];
            #pragma unroll
            for (int mt = 0; mt < 4; ++mt)
                ldsm4(a[mt][0], a[mt][1], a[mt][2], a[mt][3],
                      aB + (a_row + mt * 16) * 144 + (ks * 16 + a_kof) * 2);
            uint32_t b[8][2];
            #pragma unroll
            for (int np = 0; np < 4; ++np)
                ldsm4(b[np * 2][0], b[np * 2][1], b[np * 2 + 1][0], b[np * 2 + 1][1],
                      bB + (b_row + np * 16) * 144 + (ks * 16 + b_kof) * 2);
            #pragma unroll
            for (int mt = 0; mt < 4; ++mt)
                #pragma unroll
                for (int nt = 0; nt < 8; ++nt)
                    mma_bf16(acc[mt][nt][0], acc[mt][nt][1], acc[mt][nt][2], acc[mt][nt][3],
                             a[mt][0], a[mt][1], a[mt][2], a[mt][3],
                             b[nt][0], b[nt][1]);
        }
    }
    #undef LOAD_STAGE

    if (sOut == nullptr) {
        // direct fp32 epilogue
        #pragma unroll
        for (int mt = 0; mt < 4; ++mt) {
            #pragma unroll
            for (int half = 0; half < 2; ++half) {
                const int m = m0 + mw + mt * 16 + (lane >> 2) + half * 8;
                float* Crow = C + (size_t)m * 512;
                const float* Rrow = (mode == 1) ? res + (size_t)m * 512 : nullptr;
                #pragma unroll
                for (int nt = 0; nt < 8; ++nt) {
                    const int n = n0 + nw + nt * 8 + (lane & 3) * 2;
                    float v0 = acc[mt][nt][half * 2 + 0];
                    float v1 = acc[mt][nt][half * 2 + 1];
                    if (bias) { v0 += bias[n]; v1 += bias[n + 1]; }
                    if (mode == 1) { v0 += Rrow[n]; v1 += Rrow[n + 1]; }
                    else if (mode == 2) { v0 = gelu1(v0); v1 = gelu1(v1); }
                    float2 o; o.x = v0; o.y = v1;
                    *reinterpret_cast<float2*>(Crow + n) = o;
                }
            }
        }
    } else {
        // staged split epilogue: two 128x128 halves via smem (row stride STGS floats)
        float* stg = reinterpret_cast<float*>(smem);
        const int myhalf = wid >> 2;            // wids 0-3 -> half 0, 4-7 -> half 1
        const int nb = ((wid >> 1) & 1) * 64;   // n base within the 128 half
        #pragma unroll
        for (int half = 0; half < 2; ++half) {
            __syncthreads();   // smem free (mainloop/prior half done)
            if (myhalf == half) {
                #pragma unroll
                for (int mt = 0; mt < 4; ++mt)
                    #pragma unroll
                    for (int hh = 0; hh < 2; ++hh) {
                        const int r = mw + mt * 16 + (lane >> 2) + hh * 8;
                        #pragma unroll
                        for (int nt = 0; nt < 8; ++nt) {
                            const int cc = nb + nt * 8 + (lane & 3) * 2;
                            float v0 = acc[mt][nt][hh * 2 + 0];
                            float v1 = acc[mt][nt][hh * 2 + 1];
                            if (bias) {
                                const int n = n0 + half * 128 + cc;
                                v0 += bias[n]; v1 += bias[n + 1];
                            }
                            if (mode == 2) { v0 = gelu1(v0); v1 = gelu1(v1); }
                            float2 o; o.x = v0; o.y = v1;
                            *reinterpret_cast<float2*>(stg + r * STGS + cc) = o;
                        }
                    }
            }
            __syncthreads();
            // coalesced split write: warp handles one row per iteration
            #pragma unroll
            for (int it = 0; it < 16; ++it) {
                const int task = it * 256 + tid;      // 0..4095
                const int r = task >> 5;
                const int cq = (task & 31) * 4;
                const float4 v = *reinterpret_cast<const float4*>(stg + r * STGS + cq);
                __nv_bfloat16 hi[4], lo[4];
                const float vv[4] = {v.x, v.y, v.z, v.w};
                #pragma unroll
                for (int j = 0; j < 4; ++j) {
                    hi[j] = __float2bfloat16_rn(vv[j]);
                    lo[j] = __float2bfloat16_rn(vv[j] - __bfloat162float(hi[j]));
                }
                __nv_bfloat16* o = sOut + (size_t)(m0 + r) * 1536 + n0 + half * 128 + cq;
                const uint2 hv = *reinterpret_cast<uint2*>(hi);
                const uint2 lv = *reinterpret_cast<uint2*>(lo);
                *reinterpret_cast<uint2*>(o)        = hv;
                *reinterpret_cast<uint2*>(o + 512)  = lv;
                *reinterpret_cast<uint2*>(o + 1024) = hv;
            }
        }
    }
}

// ================= fp32 GEMM (fourier DFT/inverse) =================
__global__ __launch_bounds__(256, 2)
void k_gemm128(const float* __restrict__ A, const float* __restrict__ Bm,
               float* __restrict__ C, int Nd, int Kd) {
    __shared__ float sA[2][8][128];
    __shared__ float sB[2][8][128];
    const int tid = threadIdx.x;
    const int m0 = blockIdx.y * 128;
    const int n0 = blockIdx.x * 128;
    const int lrow = tid >> 1;
    const int lcol = (tid & 1) * 4;
    const int tx = tid & 15;
    const int ty = tid >> 4;

    const float* Aptr = A + (size_t)(m0 + lrow) * Kd + lcol;
    const bool bvalid = (n0 + lrow) < Nd;
    const float* Bptr = Bm + (size_t)(n0 + lrow) * Kd + lcol;

    float acc[8][8] = {};
    {
        const float4 a = *reinterpret_cast<const float4*>(Aptr);
        float4 b = make_float4(0.f, 0.f, 0.f, 0.f);
        if (bvalid) b = *reinterpret_cast<const float4*>(Bptr);
        sA[0][lcol + 0][lrow] = a.x; sA[0][lcol + 1][lrow] = a.y;
        sA[0][lcol + 2][lrow] = a.z; sA[0][lcol + 3][lrow] = a.w;
        sB[0][lcol + 0][lrow] = b.x; sB[0][lcol + 1][lrow] = b.y;
        sB[0][lcol + 2][lrow] = b.z; sB[0][lcol + 3][lrow] = b.w;
    }
    __syncthreads();
    const int nstages = Kd >> 3;
    int buf = 0;
    #define COMPUTE_STAGE(BUF)                                                     \
        _Pragma("unroll")                                                          \
        for (int k = 0; k < 8; ++k) {                                              \
            const float4 a0 = *reinterpret_cast<const float4*>(&sA[BUF][k][ty * 4]);      \
            const float4 a1 = *reinterpret_cast<const float4*>(&sA[BUF][k][64 + ty * 4]); \
            const float4 b0 = *reinterpret_cast<const float4*>(&sB[BUF][k][tx * 4]);      \
            const float4 b1 = *reinterpret_cast<const float4*>(&sB[BUF][k][64 + tx * 4]); \
            const float av[8] = {a0.x, a0.y, a0.z, a0.w, a1.x, a1.y, a1.z, a1.w};  \
            const float bv[8] = {b0.x, b0.y, b0.z, b0.w, b1.x, b1.y, b1.z, b1.w};  \
            _Pragma("unroll")                                                      \
            for (int i = 0; i < 8; ++i)                                            \
                _Pragma("unroll")                                                  \
                for (int j = 0; j < 8; ++j)                                        \
                    acc[i][j] += av[i] * bv[j];                                    \
        }
    for (int s = 1; s < nstages; ++s) {
        const float4 a = *reinterpret_cast<const float4*>(Aptr + (size_t)s * 8);
        float4 b = make_float4(0.f, 0.f, 0.f, 0.f);
        if (bvalid) b = *reinterpret_cast<const float4*>(Bptr + (size_t)s * 8);
        COMPUTE_STAGE(buf)
        const int nb = buf ^ 1;
        sA[nb][lcol + 0][lrow] = a.x; sA[nb][lcol + 1][lrow] = a.y;
        sA[nb][lcol + 2][lrow] = a.z; sA[nb][lcol + 3][lrow] = a.w;
        sB[nb][lcol + 0][lrow] = b.x; sB[nb][lcol + 1][lrow] = b.y;
        sB[nb][lcol + 2][lrow] = b.z; sB[nb][lcol + 3][lrow] = b.w;
        __syncthreads();
        buf = nb;
    }
    COMPUTE_STAGE(buf)
    #undef COMPUTE_STAGE

    #pragma unroll
    for (int i = 0; i < 8; ++i) {
        const int m = m0 + ((i < 4) ? (ty * 4 + i) : (64 + ty * 4 + i - 4));
        float* Crow = C + (size_t)m * Nd;
        #pragma unroll
        for (int j = 0; j < 8; ++j) {
            const int n = n0 + ((j < 4) ? (tx * 4 + j) : (64 + tx * 4 + j - 4));
            if (n >= Nd) continue;
            Crow[n] = acc[i][j];
        }
    }
}

// last column (l=256) of inverse DFT -> fp32 xq
__global__ void k_lastcol(const float* __restrict__ Ainv, const float* __restrict__ Binv,
                          float* __restrict__ xq) {
    __shared__ float sb[128];
    const int tid = threadIdx.x;
    if (tid < 128) sb[tid] = Binv[256 * 128 + tid];
    __syncthreads();
    const int r = blockIdx.x * 256 + tid;
    const float* ar = Ainv + (size_t)r * 128;
    float acc = 0.f;
    #pragma unroll 8
    for (int k = 0; k < 128; ++k) acc += ar[k] * sb[k];
    xq[(size_t)r * 257 + 256] = acc;
}

// ---------------- DFT basis tables ----------------
__global__ void k_init_cs() {
    const int idx = blockIdx.x * blockDim.x + threadIdx.x;
    if (idx >= 128 * LP_) return;
    const int n = idx / LP_;
    const int l = idx % LP_;
    float v = 0.f;
    if (l < L_) {
        const int m = (n < M_) ? n : (n - M_);
        const long r = ((long)m * l) % L_;
        const double ang = 6.283185307179586476925 * (double)r / (double)L_;
        v = (n < M_) ? (float)cos(ang) : (float)(-sin(ang));
    }
    g_cs[idx] = v;
}
__global__ void k_init_binv() {
    const int idx = blockIdx.x * blockDim.x + threadIdx.x;
    if (idx >= L_ * 2 * M_) return;
    const int t = idx / (2 * M_);
    const int k = idx % (2 * M_);
    const int m = (k < M_) ? k : (k - M_);
    const long r = ((long)t * m) % L_;
    const double ang = 6.283185307179586476925 * (double)r / (double)L_;
    g_Binv[idx] = (k < M_) ? (float)cos(ang) : (float)(-sin(ang));
}
__global__ void k_padzero() {
    const int idx = blockIdx.x * blockDim.x + threadIdx.x;
    const int nrows = BE_ * D_;
    if (idx >= nrows * (LP_ - L_)) return;
    const int row = idx / (LP_ - L_);
    const int c   = idx % (LP_ - L_);
    g_xqp[(size_t)row * LP_ + L_ + c] = 0.f;
}

// ---------------- token embedding prep ----------------
__global__ void k_w2t(const float* __restrict__ tok_w) {
    const int idx = blockIdx.x * blockDim.x + threadIdx.x;
    if (idx >= D_ * K3) return;
    const int o = idx / K3;
    const int c = idx % K3;
    const int k = c / CIN_;
    const int i = c % CIN_;
    g_W2t[idx] = tok_w[(o * CIN_ + i) * 3 + k];
}
__global__ void k_xcat(const float* __restrict__ x, const float* __restrict__ cls,
                       __nv_bfloat16* __restrict__ sOut) {
    const size_t idx = (size_t)blockIdx.x * blockDim.x + threadIdx.x;
    if (idx >= (size_t)BE_ * L_ * K3) return;
    const int c  = (int)(idx % K3);
    const int l  = (int)((idx / K3) % L_);
    const int be = (int)(idx / ((size_t)K3 * L_));
    const int k = c / CIN_;
    const int i = c % CIN_;
    const int ls = (l + k - 1 + L_) % L_;
    const int b  = be / CH_;
    const int ch = be % CH_;
    float v;
    if (ls == 0) v = cls[ch * CIN_ + i];
    else         v = x[(((size_t)b * T_ + (ls - 1)) * CH_ + ch) * CIN_ + i];
    write_split(sOut + (size_t)(be * L_ + l) * 576 + c, K3, v);
}
__global__ void k_posadd(__nv_bfloat16* __restrict__ sOut) {
    const size_t idx = (size_t)blockIdx.x * blockDim.x + threadIdx.x;
    if (idx >= (size_t)BE_ * L_ * D_) return;
    const int d = (int)(idx & 511);
    const int l = (int)((idx >> 9) % L_);
    const int j = d >> 1;
    const float div = expf(-(float)(2 * j) * (9.210340371976184f / (float)D_));
    const float ang = (float)l * div;
    const float v = g_h[idx] + ((d & 1) ? cosf(ang) : sinf(ang));
    g_h[idx] = v;
    write_split(sOut + (idx >> 9) * 1536 + d, 512, v);
}

// ---------------- batched transpose ----------------
__global__ void k_transpose(const float* __restrict__ in, float* __restrict__ out,
                            int Rr, int Cc, int os) {
    __shared__ float tile[32][33];
    const int b  = blockIdx.z;
    const int r0 = blockIdx.y * 32;
    const int c0 = blockIdx.x * 32;
    const int x = threadIdx.x;
    const int y = threadIdx.y;
    #pragma unroll
    for (int yy = y; yy < 32; yy += 8) {
        const int r = r0 + yy, c = c0 + x;
        if (r < Rr && c < Cc) tile[yy][x] = in[((size_t)b * Rr + r) * Cc + c];
    }
    __syncthreads();
    #pragma unroll
    for (int yy = y; yy < 32; yy += 8) {
        const int c = c0 + yy, r = r0 + x;
        if (r < Rr && c < Cc) out[((size_t)b * Cc + c) * os + r] = tile[x][yy];
    }
}

// ---------------- complex frequency mixing ----------------
__global__ void k_mix2(const float* __restrict__ X,
                       const float* __restrict__ fwr, const float* __restrict__ fwi,
                       float* __restrict__ Ainv) {
    const int hh = blockIdx.x;
    const int m  = blockIdx.y;
    const int tid = threadIdx.x;
    __shared__ float sWr[64][64];
    __shared__ float sWi[64][64];
    __shared__ float sXr[4][64];
    __shared__ float sXi[4][64];
    for (int idx = tid; idx < 4096; idx += 256) {
        const int i = idx >> 6, o = idx & 63;
        const size_t w = (((size_t)hh * 64 + i) * 64 + o) * 64 + m;
        sWr[i][o] = fwr[w];
        sWi[i][o] = fwi[w];
    }
    __syncthreads();
    const int o    = tid & 63;
    const int bloc = tid >> 6;
    const float cm = ((m == 0) ? 1.f : 2.f) / (float)L_;
    for (int be0 = 0; be0 < BE_; be0 += 4) {
        {
            const int i = tid & 63, bl = tid >> 6;
            const size_t xr = ((size_t)(be0 + bl) * D_ + hh * 64 + i) * 128 + m;
            sXr[bl][i] = X[xr];
            sXi[bl][i] = X[xr + 64];
        }
        __syncthreads();
        float ar = 0.f, ai = 0.f;
        #pragma unroll 8
        for (int i = 0; i < 64; ++i) {
            const float xr = sXr[bloc][i], xi = sXi[bloc][i];
            const float wr = sWr[i][o],    wi = sWi[i][o];
            ar += xr * wr - xi * wi;
            ai += xr * wi + xi * wr;
        }
        const size_t row = (size_t)(be0 + bloc) * D_ + hh * 64 + o;
        Ainv[row * 128 + m]      = cm * ar;
        Ainv[row * 128 + 64 + m] = cm * ai;
        __syncthreads();
    }
}

// ---------------- series_decomp residual with fused split ----------------
__global__ void k_movmean(float* __restrict__ hbuf, __nv_bfloat16* __restrict__ sOut) {
    const int be = blockIdx.x;
    const int d0 = blockIdx.y * 32;
    __shared__ float s[L_ * 32];
    const int tid = threadIdx.x;
    for (int idx = tid; idx < L_ * 32; idx += 256) {
        const int l = idx >> 5, dd = idx & 31;
        s[idx] = hbuf[((size_t)be * L_ + l) * D_ + d0 + dd];
    }
    __syncthreads();
    for (int idx = tid; idx < L_ * 32; idx += 256) {
        const int l = idx >> 5, dd = idx & 31;
        float acc = 0.f;
        #pragma unroll
        for (int j = -12; j <= 12; ++j) {
            int jj = l + j;
            jj = jj < 0 ? 0 : (jj > L_ - 1 ? L_ - 1 : jj);
            acc += s[(jj << 5) + dd];
        }
        const float v = s[idx] - acc * (1.f / 25.f);
        const size_t row = (size_t)be * L_ + l;
        hbuf[row * D_ + d0 + dd] = v;
        write_split(sOut + row * 1536 + d0 + dd, 512, v);
    }
}

// ---------------- final LayerNorm + mean-pool ----------------
__global__ void k_lnpool(const float* __restrict__ g, const float* __restrict__ b) {
    const int be = blockIdx.x;
    const int tid = threadIdx.x;
    __shared__ float ws[16], ws2[16];
    const int wid = tid >> 5, lane = tid & 31;
    const float gg = g[tid], bb = b[tid];
    float acc = 0.f;
    for (int l = 0; l < L_; ++l) {
        const float v = g_h[((size_t)be * L_ + l) * D_ + tid];
        float s = v, s2 = v * v;
        #pragma unroll
        for (int off = 16; off > 0; off >>= 1) {
            s  += __shfl_xor_sync(0xffffffffu, s, off);
            s2 += __shfl_xor_sync(0xffffffffu, s2, off);
        }
        if (lane == 0) { ws[wid] = s; ws2[wid] = s2; }
        __syncthreads();
        float tot = 0.f, tot2 = 0.f;
        #pragma unroll
        for (int w = 0; w < 16; ++w) { tot += ws[w]; tot2 += ws2[w]; }
        const float mu  = tot * (1.f / (float)D_);
        const float var = tot2 * (1.f / (float)D_) - mu * mu;
        const float inv = rsqrtf(var + 1e-5f);
        acc += (v - mu) * inv * gg + bb;
        __syncthreads();
    }
    g_z[(size_t)be * D_ + tid] = acc * (1.f / (float)L_);
}

// ---------------- decoders ----------------
__global__ void k_dec1(const float* __restrict__ w, const float* __restrict__ b1) {
    const int tid = threadIdx.x;
    const int warp = tid >> 5, lane = tid & 31;
    const int idx = blockIdx.x * 8 + warp;
    const int bb = idx >> 9;
    const int oo = idx & 511;
    const float* zr = g_z + (size_t)bb * (CH_ * D_);
    const float* wr = w   + (size_t)oo * (CH_ * D_);
    float acc = 0.f;
    for (int k = lane * 4; k < CH_ * D_; k += 128) {
        const float4 zv = *reinterpret_cast<const float4*>(zr + k);
        const float4 wv = *reinterpret_cast<const float4*>(wr + k);
        acc += zv.x * wv.x + zv.y * wv.y + zv.z * wv.z + zv.w * wv.w;
    }
    #pragma unroll
    for (int off = 16; off > 0; off >>= 1) acc += __shfl_xor_sync(0xffffffffu, acc, off);
    if (lane == 0) {
        const float v = acc + b1[oo];
        g_z2[idx] = gelu1(v);
    }
}
__global__ void k_dec2(const float* __restrict__ w, const float* __restrict__ bias,
                       float* __restrict__ out) {
    const int bb = blockIdx.x;
    const int tid = threadIdx.x;
    float acc = 0.f;
    for (int d = tid; d < D_; d += 128) acc += g_z2[bb * D_ + d] * w[d];
    #pragma unroll
    for (int off = 16; off > 0; off >>= 1) acc += __shfl_xor_sync(0xffffffffu, acc, off);
    __shared__ float ws[4];
    if ((tid & 31) == 0) ws[tid >> 5] = acc;
    __syncthreads();
    if (tid == 0) out[bb] = ws[0] + ws[1] + ws[2] + ws[3] + bias[0];
}

// ---------------- orchestration ----------------
extern "C" void kernel_launch(void* const* d_in, const int* in_sizes, int n_in,
                              void* d_out, int out_size) {
    const float* x     = (const float*)d_in[0];
    const float* cls   = (const float*)d_in[3];
    const float* tok_w = (const float*)d_in[4];
    const float* wq    = (const float*)d_in[5];
    const float* bq    = (const float*)d_in[6];
    const float* wo    = (const float*)d_in[7];
    const float* bo    = (const float*)d_in[8];
    const float* c1w   = (const float*)d_in[9];
    const float* c2w   = (const float*)d_in[10];
    const float* fwr   = (const float*)d_in[11];
    const float* fwi   = (const float*)d_in[12];
    const float* ng    = (const float*)d_in[13];
    const float* nb    = (const float*)d_in[14];
    const float* d1w   = (const float*)d_in[15];
    const float* d1b   = (const float*)d_in[16];
    const float* d2w   = (const float*)d_in[17];
    const float* d2b   = (const float*)d_in[18];
    float* out = (float*)d_out;

    float *ph, *pq, *pt, *pxq, *pxqp, *pW2t, *pcs, *pBinv;
    __nv_bfloat16 *pA2a, *pA2b, *pB2;
    cudaGetSymbolAddress((void**)&ph,    g_h);
    cudaGetSymbolAddress((void**)&pq,    g_q);
    cudaGetSymbolAddress((void**)&pt,    g_t);
    cudaGetSymbolAddress((void**)&pxq,   g_xq);
    cudaGetSymbolAddress((void**)&pxqp,  g_xqp);
    cudaGetSymbolAddress((void**)&pW2t,  g_W2t);
    cudaGetSymbolAddress((void**)&pcs,   g_cs);
    cudaGetSymbolAddress((void**)&pBinv, g_Binv);
    cudaGetSymbolAddress((void**)&pA2a,  g_A2a);
    cudaGetSymbolAddress((void**)&pA2b,  g_A2b);
    cudaGetSymbolAddress((void**)&pB2,   g_B2);

    float* pX    = pq;
    float* pAinv = pt;

    cudaFuncSetAttribute(k_mma, cudaFuncAttributeMaxDynamicSharedMemorySize, SMEM_MMA);

    const dim3 gTC(2, MR / 128);            // 128x256 CTA tiles
    const dim3 gemmDft(1, R_ / 128);
    const dim3 gemmInv(2, R_ / 128);
    const int splitAblk  = (MR * D_ / 4 + 255) / 256;
    const int splitWblk  = (D_ * D_ / 4 + 255) / 256;
    const int splitW3blk = (D_ * K3 / 4 + 255) / 256;

    // tables first (independent of inputs)
    k_init_cs  <<<(128 * LP_ + 255) / 256, 256>>>();
    k_init_binv<<<(L_ * 2 * M_ + 255) / 256, 256>>>();
    k_padzero  <<<(BE_ * D_ * (LP_ - L_) + 255) / 256, 256>>>();

    // embedding
    k_w2t <<<(D_ * K3 + 255) / 256, 256>>>(tok_w);
    k_xcat<<<(int)(((size_t)BE_ * L_ * K3 + 255) / 256), 256>>>(x, cls, pA2a);
    k_splitW<<<splitW3blk, 256>>>(pW2t, pB2, K3, D_ * K3 / 4);
    k_mma<<<gTC, 256, SMEM_MMA>>>(pA2a, pB2, ph, nullptr, nullptr, 3 * K3, 0, nullptr);
    k_posadd<<<(int)(((size_t)BE_ * L_ * D_ + 255) / 256), 256>>>(pA2a);

    for (int l = 0; l < NL_; ++l) {
        const float* wql = wq + (size_t)l * D_ * D_;
        const float* bql = bq + (size_t)l * D_;
        const float* wol = wo + (size_t)l * D_ * D_;
        const float* bol = bo + (size_t)l * D_;
        const float* c1l = c1w + (size_t)l * D_ * D_;
        const float* c2l = c2w + (size_t)l * D_ * D_;

        k_splitW<<<splitWblk, 256>>>(wql, pB2, D_, D_ * D_ / 4);
        k_mma<<<gTC, 256, SMEM_MMA>>>(pA2a, pB2, pq, bql, nullptr, 3 * D_, 0, nullptr);
        k_transpose<<<dim3(D_ / 32, (L_ + 31) / 32, BE_), dim3(32, 8)>>>(pq, pxqp, L_, D_, LP_);
        k_gemm128<<<gemmDft, 256>>>(pxqp, pcs, pX, 128, LP_);
        k_mix2<<<dim3(H_, M_), 256>>>(pX, fwr, fwi, pAinv);
        k_gemm128<<<gemmInv, 256>>>(pAinv, pBinv, pxq, 257, 2 * M_);
        k_lastcol<<<R_ / 256, 256>>>(pAinv, pBinv, pxq);
        k_split<<<splitAblk, 256>>>(pxq, pA2b, D_, MR * D_ / 4);
        k_splitW<<<splitWblk, 256>>>(wol, pB2, D_, D_ * D_ / 4);
        k_mma<<<gTC, 256, SMEM_MMA>>>(pA2b, pB2, ph, bol, ph, 3 * D_, 1, nullptr);
        k_movmean<<<dim3(BE_, D_ / 32), 256>>>(ph, pA2a);
        // conv1: gelu + staged split directly to A2b (no fp32 t, no k_split pass)
        k_splitW<<<splitWblk, 256>>>(c1l, pB2, D_, D_ * D_ / 4);
        k_mma<<<gTC, 256, SMEM_MMA>>>(pA2a, pB2, nullptr, nullptr, nullptr, 3 * D_, 2, pA2b);
        k_splitW<<<splitWblk, 256>>>(c2l, pB2, D_, D_ * D_ / 4);
        k_mma<<<gTC, 256, SMEM_MMA>>>(pA2b, pB2, ph, nullptr, ph, 3 * D_, 1, nullptr);
        k_movmean<<<dim3(BE_, D_ / 32), 256>>>(ph, pA2a);
    }

    k_lnpool<<<BE_, 512>>>(ng, nb);
    k_dec1<<<B_ * D_ / 8, 256>>>(d1w, d1b);
    k_dec2<<<B_, 128>>>(d2w, d2b, out);
}

// round 15
// speedup vs baseline: 1.1373x; 1.1373x over previous
#include <cuda_runtime.h>
#include <cuda_bf16.h>
#include <math.h>
#include <stdint.h>

// ---------------- problem constants ----------------
constexpr int B_   = 16;
constexpr int T_   = 256;
constexpr int CH_  = 16;
constexpr int CIN_ = 64;
constexpr int D_   = 512;
constexpr int H_   = 8;
constexpr int E_   = 64;
constexpr int NL_  = 2;
constexpr int M_   = 64;
constexpr int L_   = T_ + 1; // 257
constexpr int LP_  = 264;
constexpr int BE_  = B_ * CH_;      // 256
constexpr int MR   = BE_ * L_;      // 65792 = 514*128
constexpr int R_   = BE_ * D_;      // 131072
constexpr int K3   = 3 * CIN_;      // 192

// ---------------- scratch ----------------
__device__ float g_h   [(size_t)BE_ * L_ * D_];
__device__ float g_q   [(size_t)BE_ * L_ * D_];
__device__ float g_t   [(size_t)BE_ * L_ * D_];   // Ainv alias + conv1 fp32 out
__device__ float g_xq  [(size_t)BE_ * D_ * L_];   // inverse output; 2nd half holds X2
__device__ float g_W2t [(size_t)D_ * K3];
__device__ float g_cs  [128 * LP_];               // cs[m, l], zero-padded l>=257
__device__ float g_Binv[L_ * 2 * M_];
__device__ float g_z  [BE_ * D_];
__device__ float g_z2 [B_ * D_];
__device__ __nv_bfloat16 g_A2a[(size_t)MR * 3 * D_];  // split activations (ping)
__device__ __nv_bfloat16 g_A2b[(size_t)MR * 3 * D_];  // split activations (pong)
__device__ __nv_bfloat16 g_B2 [(size_t)D_ * 3 * D_];  // split weights [hi|hi|lo]

// ================= helpers =================
__device__ __forceinline__ uint32_t smem_u32(const void* p) {
    uint32_t a;
    asm("{ .reg .u64 t; cvta.to.shared.u64 t, %1; cvt.u32.u64 %0, t; }" : "=r"(a) : "l"(p));
    return a;
}
__device__ __forceinline__ void ldsm4(uint32_t& r0, uint32_t& r1, uint32_t& r2, uint32_t& r3,
                                      uint32_t a) {
    asm volatile("ldmatrix.sync.aligned.m8n8.x4.shared.b16 {%0,%1,%2,%3}, [%4];"
                 : "=r"(r0), "=r"(r1), "=r"(r2), "=r"(r3) : "r"(a));
}
__device__ __forceinline__ void mma_bf16(float& d0, float& d1, float& d2, float& d3,
                                         uint32_t a0, uint32_t a1, uint32_t a2, uint32_t a3,
                                         uint32_t b0, uint32_t b1) {
    asm volatile("mma.sync.aligned.m16n8k16.row.col.f32.bf16.bf16.f32 "
                 "{%0,%1,%2,%3}, {%4,%5,%6,%7}, {%8,%9}, {%0,%1,%2,%3};"
                 : "+f"(d0), "+f"(d1), "+f"(d2), "+f"(d3)
                 : "r"(a0), "r"(a1), "r"(a2), "r"(a3), "r"(b0), "r"(b1));
}
__device__ __forceinline__ void cp16(uint32_t dst, const void* src) {
    asm volatile("cp.async.cg.shared.global [%0], [%1], 16;"
                 :: "r"(dst), "l"(__cvta_generic_to_global(src)) : "memory");
}
// A-side split layout [hi | lo | hi]
__device__ __forceinline__ void write_split(__nv_bfloat16* o, int K, float v) {
    const __nv_bfloat16 hi = __float2bfloat16_rn(v);
    const __nv_bfloat16 lo = __float2bfloat16_rn(v - __bfloat162float(hi));
    o[0] = hi; o[K] = lo; o[2 * K] = hi;
}
__device__ __forceinline__ float gelu1(float v) {
    return 0.5f * v * (1.f + erff(v * 0.70710678118654752f));
}

// ========== standalone A-split: fp32 [rows,K] -> bf16 [rows,3K] = [hi|lo|hi] ==========
__global__ void k_split(const float* __restrict__ A, __nv_bfloat16* __restrict__ out,
                        int K, int total4) {
    const int idx = blockIdx.x * blockDim.x + threadIdx.x;
    if (idx >= total4) return;
    const int Kq = K >> 2;
    const int row = idx / Kq;
    const int c   = (idx - row * Kq) << 2;
    const float4 v = *reinterpret_cast<const float4*>(A + (size_t)row * K + c);
    __nv_bfloat16 hi[4], lo[4];
    const float vv[4] = {v.x, v.y, v.z, v.w};
    #pragma unroll
    for (int j = 0; j < 4; ++j) {
        hi[j] = __float2bfloat16_rn(vv[j]);
        lo[j] = __float2bfloat16_rn(vv[j] - __bfloat162float(hi[j]));
    }
    __nv_bfloat16* o = out + (size_t)row * (3 * K);
    const uint2 hv = *reinterpret_cast<uint2*>(hi);
    const uint2 lv = *reinterpret_cast<uint2*>(lo);
    *reinterpret_cast<uint2*>(o + c)         = hv;
    *reinterpret_cast<uint2*>(o + K + c)     = lv;
    *reinterpret_cast<uint2*>(o + 2 * K + c) = hv;
}

// ========== weight split: [hi|hi|lo] ==========
__global__ void k_splitW(const float* __restrict__ A, __nv_bfloat16* __restrict__ out,
                         int K, int total4) {
    const int idx = blockIdx.x * blockDim.x + threadIdx.x;
    if (idx >= total4) return;
    const int Kq = K >> 2;
    const int row = idx / Kq;
    const int c   = (idx - row * Kq) << 2;
    const float4 v = *reinterpret_cast<const float4*>(A + (size_t)row * K + c);
    __nv_bfloat16 hi[4], lo[4];
    const float vv[4] = {v.x, v.y, v.z, v.w};
    #pragma unroll
    for (int j = 0; j < 4; ++j) {
        hi[j] = __float2bfloat16_rn(vv[j]);
        lo[j] = __float2bfloat16_rn(vv[j] - __bfloat162float(hi[j]));
    }
    __nv_bfloat16* o = out + (size_t)row * (3 * K);
    const uint2 hv = *reinterpret_cast<uint2*>(hi);
    const uint2 lv = *reinterpret_cast<uint2*>(lo);
    *reinterpret_cast<uint2*>(o + c)         = hv;
    *reinterpret_cast<uint2*>(o + K + c)     = hv;
    *reinterpret_cast<uint2*>(o + 2 * K + c) = lv;
}

// ================= bf16 mma.sync GEMM (R11-proven): C[M,512] = A2 @ B2^T =============
// CTA tile 128x256 (grid.x == 2), 8 warps, warp tile 64x64, 2-stage cp.async (110,592 B).
// mode 0: +bias ; 1: +bias+res ; 2: gelu(+bias)
constexpr int STAGE_BYTES = 384 * 144;
constexpr int SMEM_MMA    = 2 * STAGE_BYTES;     // 110592

__global__ __launch_bounds__(256, 1)
void k_mma(const __nv_bfloat16* __restrict__ A2, const __nv_bfloat16* __restrict__ B2,
           float* __restrict__ C, const float* __restrict__ bias,
           const float* __restrict__ res, int K2, int mode) {
    extern __shared__ char smem[];
    const uint32_t sb = smem_u32(smem);
    const int tid = threadIdx.x;
    const int wid = tid >> 5, lane = tid & 31;
    const int mw = (wid & 1) * 64;
    const int nw = (wid >> 1) * 64;
    const int m0 = blockIdx.y * 128;
    const int n0 = blockIdx.x * 256;

    float acc[4][8][4] = {};
    const int nch = K2 >> 6;

    #define LOAD_STAGE(c, s) do {                                                   \
        const uint32_t base = sb + (s) * STAGE_BYTES;                               \
        _Pragma("unroll")                                                           \
        for (int i = 0; i < 12; ++i) {                                              \
            const int idx = i * 256 + tid;                                          \
            const int r = idx >> 3, sg = idx & 7;                                   \
            const __nv_bfloat16* src = (r < 128)                                    \
                ? A2 + (size_t)(m0 + r) * K2 + (c) * 64 + sg * 8                    \
                : B2 + (size_t)(n0 + r - 128) * K2 + (c) * 64 + sg * 8;             \
            cp16(base + r * 144 + sg * 16, src);                                    \
        }                                                                           \
        asm volatile("cp.async.commit_group;" ::: "memory");                        \
    } while (0)

    LOAD_STAGE(0, 0);

    const int a_row = mw + (lane & 15);
    const int a_kof = (lane >> 4) * 8;
    const int b_row = nw + ((lane >> 4) << 3) + (lane & 7);
    const int b_kof = ((lane >> 3) & 1) * 8;

    for (int c = 0; c < nch; ++c) {
        asm volatile("cp.async.wait_group 0;" ::: "memory");
        __syncthreads();
        if (c + 1 < nch) LOAD_STAGE(c + 1, (c + 1) & 1);

        const uint32_t aB = sb + (c & 1) * STAGE_BYTES;
        const uint32_t bB = aB + 128 * 144;

        #pragma unroll
        for (int ks = 0; ks < 4; ++ks) {
            uint32_t a[4][4];
            #pragma unroll
            for (int mt = 0; mt < 4; ++mt)
                ldsm4(a[mt][0], a[mt][1], a[mt][2], a[mt][3],
                      aB + (a_row + mt * 16) * 144 + (ks * 16 + a_kof) * 2);
            uint32_t b[8][2];
            #pragma unroll
            for (int np = 0; np < 4; ++np)
                ldsm4(b[np * 2][0], b[np * 2][1], b[np * 2 + 1][0], b[np * 2 + 1][1],
                      bB + (b_row + np * 16) * 144 + (ks * 16 + b_kof) * 2);
            #pragma unroll
            for (int mt = 0; mt < 4; ++mt)
                #pragma unroll
                for (int nt = 0; nt < 8; ++nt)
                    mma_bf16(acc[mt][nt][0], acc[mt][nt][1], acc[mt][nt][2], acc[mt][nt][3],
                             a[mt][0], a[mt][1], a[mt][2], a[mt][3],
                             b[nt][0], b[nt][1]);
        }
    }
    #undef LOAD_STAGE

    #pragma unroll
    for (int mt = 0; mt < 4; ++mt) {
        #pragma unroll
        for (int half = 0; half < 2; ++half) {
            const int m = m0 + mw + mt * 16 + (lane >> 2) + half * 8;
            float* Crow = C + (size_t)m * 512;
            const float* Rrow = (mode == 1) ? res + (size_t)m * 512 : nullptr;
            #pragma unroll
            for (int nt = 0; nt < 8; ++nt) {
                const int n = n0 + nw + nt * 8 + (lane & 3) * 2;
                float v0 = acc[mt][nt][half * 2 + 0];
                float v1 = acc[mt][nt][half * 2 + 1];
                if (bias) { v0 += bias[n]; v1 += bias[n + 1]; }
                if (mode == 1) { v0 += Rrow[n]; v1 += Rrow[n + 1]; }
                else if (mode == 2) { v0 = gelu1(v0); v1 = gelu1(v1); }
                float2 o; o.x = v0; o.y = v1;
                *reinterpret_cast<float2*>(Crow + n) = o;
            }
        }
    }
}

// ============ batched DFT NN-GEMM: X2[be](128x512) = cs(128xL) @ q[be](Lx512) ==========
// grid (4, 1, BE). A=cs row-major (stride LP, zero-padded l>=257); B=q[be] row-major.
__global__ __launch_bounds__(256, 2)
void k_dftb(const float* __restrict__ cs, const float* __restrict__ q,
            float* __restrict__ X2) {
    __shared__ float sA[2][8][128];
    __shared__ float sB[2][8][128];
    const int tid = threadIdx.x;
    const int be = blockIdx.z;
    const int n0 = blockIdx.x * 128;
    const float* qb = q + (size_t)be * L_ * D_;
    float* Xb = X2 + (size_t)be * 128 * D_;

    const int lrow = tid >> 1;          // A: m row 0..127
    const int lcol = (tid & 1) * 4;     // A: k sub 0 or 4
    const int bkk = tid >> 5;           // B: k row 0..7
    const int bn  = (tid & 31) * 4;     // B: n sub
    const int tx = tid & 15, ty = tid >> 4;

    float acc[8][8] = {};
    {
        const float4 a = *reinterpret_cast<const float4*>(cs + (size_t)lrow * LP_ + lcol);
        sA[0][lcol + 0][lrow] = a.x; sA[0][lcol + 1][lrow] = a.y;
        sA[0][lcol + 2][lrow] = a.z; sA[0][lcol + 3][lrow] = a.w;
        float4 b = make_float4(0.f, 0.f, 0.f, 0.f);
        if (bkk < L_) b = *reinterpret_cast<const float4*>(qb + (size_t)bkk * D_ + n0 + bn);
        *reinterpret_cast<float4*>(&sB[0][bkk][bn]) = b;
    }
    __syncthreads();
    const int nstages = LP_ >> 3;   // 33
    int buf = 0;
    #define DFT_STAGE(BUF)                                                          \
        _Pragma("unroll")                                                           \
        for (int k = 0; k < 8; ++k) {                                               \
            const float4 a0 = *reinterpret_cast<const float4*>(&sA[BUF][k][ty * 4]);       \
            const float4 a1 = *reinterpret_cast<const float4*>(&sA[BUF][k][64 + ty * 4]);  \
            const float4 b0 = *reinterpret_cast<const float4*>(&sB[BUF][k][tx * 4]);       \
            const float4 b1 = *reinterpret_cast<const float4*>(&sB[BUF][k][64 + tx * 4]);  \
            const float av[8] = {a0.x, a0.y, a0.z, a0.w, a1.x, a1.y, a1.z, a1.w};   \
            const float bv[8] = {b0.x, b0.y, b0.z, b0.w, b1.x, b1.y, b1.z, b1.w};   \
            _Pragma("unroll")                                                       \
            for (int i = 0; i < 8; ++i)                                             \
                _Pragma("unroll")                                                   \
                for (int j = 0; j < 8; ++j)                                         \
                    acc[i][j] += av[i] * bv[j];                                     \
        }
    for (int s = 1; s < nstages; ++s) {
        const int k0 = s * 8;
        const float4 a = *reinterpret_cast<const float4*>(cs + (size_t)lrow * LP_ + k0 + lcol);
        float4 b = make_float4(0.f, 0.f, 0.f, 0.f);
        if (k0 + bkk < L_) b = *reinterpret_cast<const float4*>(qb + (size_t)(k0 + bkk) * D_ + n0 + bn);
        DFT_STAGE(buf)
        const int nb = buf ^ 1;
        sA[nb][lcol + 0][lrow] = a.x; sA[nb][lcol + 1][lrow] = a.y;
        sA[nb][lcol + 2][lrow] = a.z; sA[nb][lcol + 3][lrow] = a.w;
        *reinterpret_cast<float4*>(&sB[nb][bkk][bn]) = b;
        __syncthreads();
        buf = nb;
    }
    DFT_STAGE(buf)
    #undef DFT_STAGE

    #pragma unroll
    for (int i = 0; i < 8; ++i) {
        const int m = (i < 4) ? (ty * 4 + i) : (64 + ty * 4 + i - 4);
        float* Crow = Xb + (size_t)m * D_;
        #pragma unroll
        for (int j = 0; j < 8; ++j) {
            const int n = n0 + ((j < 4) ? (tx * 4 + j) : (64 + tx * 4 + j - 4));
            Crow[n] = acc[i][j];
        }
    }
}

// ================= fp32 GEMM (inverse DFT) =================
__global__ __launch_bounds__(256, 2)
void k_gemm128(const float* __restrict__ A, const float* __restrict__ Bm,
               float* __restrict__ C, int Nd, int Kd) {
    __shared__ float sA[2][8][128];
    __shared__ float sB[2][8][128];
    const int tid = threadIdx.x;
    const int m0 = blockIdx.y * 128;
    const int n0 = blockIdx.x * 128;
    const int lrow = tid >> 1;
    const int lcol = (tid & 1) * 4;
    const int tx = tid & 15;
    const int ty = tid >> 4;

    const float* Aptr = A + (size_t)(m0 + lrow) * Kd + lcol;
    const bool bvalid = (n0 + lrow) < Nd;
    const float* Bptr = Bm + (size_t)(n0 + lrow) * Kd + lcol;

    float acc[8][8] = {};
    {
        const float4 a = *reinterpret_cast<const float4*>(Aptr);
        float4 b = make_float4(0.f, 0.f, 0.f, 0.f);
        if (bvalid) b = *reinterpret_cast<const float4*>(Bptr);
        sA[0][lcol + 0][lrow] = a.x; sA[0][lcol + 1][lrow] = a.y;
        sA[0][lcol + 2][lrow] = a.z; sA[0][lcol + 3][lrow] = a.w;
        sB[0][lcol + 0][lrow] = b.x; sB[0][lcol + 1][lrow] = b.y;
        sB[0][lcol + 2][lrow] = b.z; sB[0][lcol + 3][lrow] = b.w;
    }
    __syncthreads();
    const int nstages = Kd >> 3;
    int buf = 0;
    #define COMPUTE_STAGE(BUF)                                                     \
        _Pragma("unroll")                                                          \
        for (int k = 0; k < 8; ++k) {                                              \
            const float4 a0 = *reinterpret_cast<const float4*>(&sA[BUF][k][ty * 4]);      \
            const float4 a1 = *reinterpret_cast<const float4*>(&sA[BUF][k][64 + ty * 4]); \
            const float4 b0 = *reinterpret_cast<const float4*>(&sB[BUF][k][tx * 4]);      \
            const float4 b1 = *reinterpret_cast<const float4*>(&sB[BUF][k][64 + tx * 4]); \
            const float av[8] = {a0.x, a0.y, a0.z, a0.w, a1.x, a1.y, a1.z, a1.w};  \
            const float bv[8] = {b0.x, b0.y, b0.z, b0.w, b1.x, b1.y, b1.z, b1.w};  \
            _Pragma("unroll")                                                      \
            for (int i = 0; i < 8; ++i)                                            \
                _Pragma("unroll")                                                  \
                for (int j = 0; j < 8; ++j)                                        \
                    acc[i][j] += av[i] * bv[j];                                    \
        }
    for (int s = 1; s < nstages; ++s) {
        const float4 a = *reinterpret_cast<const float4*>(Aptr + (size_t)s * 8);
        float4 b = make_float4(0.f, 0.f, 0.f, 0.f);
        if (bvalid) b = *reinterpret_cast<const float4*>(Bptr + (size_t)s * 8);
        COMPUTE_STAGE(buf)
        const int nb = buf ^ 1;
        sA[nb][lcol + 0][lrow] = a.x; sA[nb][lcol + 1][lrow] = a.y;
        sA[nb][lcol + 2][lrow] = a.z; sA[nb][lcol + 3][lrow] = a.w;
        sB[nb][lcol + 0][lrow] = b.x; sB[nb][lcol + 1][lrow] = b.y;
        sB[nb][lcol + 2][lrow] = b.z; sB[nb][lcol + 3][lrow] = b.w;
        __syncthreads();
        buf = nb;
    }
    COMPUTE_STAGE(buf)
    #undef COMPUTE_STAGE

    #pragma unroll
    for (int i = 0; i < 8; ++i) {
        const int m = m0 + ((i < 4) ? (ty * 4 + i) : (64 + ty * 4 + i - 4));
        float* Crow = C + (size_t)m * Nd;
        #pragma unroll
        for (int j = 0; j < 8; ++j) {
            const int n = n0 + ((j < 4) ? (tx * 4 + j) : (64 + tx * 4 + j - 4));
            if (n >= Nd) continue;
            Crow[n] = acc[i][j];
        }
    }
}

// last column (l=256) of inverse DFT -> fp32 xq
__global__ void k_lastcol(const float* __restrict__ Ainv, const float* __restrict__ Binv,
                          float* __restrict__ xq) {
    __shared__ float sb[128];
    const int tid = threadIdx.x;
    if (tid < 128) sb[tid] = Binv[256 * 128 + tid];
    __syncthreads();
    const int r = blockIdx.x * 256 + tid;
    const float* ar = Ainv + (size_t)r * 128;
    float acc = 0.f;
    #pragma unroll 8
    for (int k = 0; k < 128; ++k) acc += ar[k] * sb[k];
    xq[(size_t)r * 257 + 256] = acc;
}

// ---------------- DFT basis tables ----------------
__global__ void k_init_cs() {
    const int idx = blockIdx.x * blockDim.x + threadIdx.x;
    if (idx >= 128 * LP_) return;
    const int n = idx / LP_;
    const int l = idx % LP_;
    float v = 0.f;
    if (l < L_) {
        const int m = (n < M_) ? n : (n - M_);
        const long r = ((long)m * l) % L_;
        const double ang = 6.283185307179586476925 * (double)r / (double)L_;
        v = (n < M_) ? (float)cos(ang) : (float)(-sin(ang));
    }
    g_cs[idx] = v;
}
__global__ void k_init_binv() {
    const int idx = blockIdx.x * blockDim.x + threadIdx.x;
    if (idx >= L_ * 2 * M_) return;
    const int t = idx / (2 * M_);
    const int k = idx % (2 * M_);
    const int m = (k < M_) ? k : (k - M_);
    const long r = ((long)t * m) % L_;
    const double ang = 6.283185307179586476925 * (double)r / (double)L_;
    g_Binv[idx] = (k < M_) ? (float)cos(ang) : (float)(-sin(ang));
}

// ---------------- token embedding prep ----------------
__global__ void k_w2t(const float* __restrict__ tok_w) {
    const int idx = blockIdx.x * blockDim.x + threadIdx.x;
    if (idx >= D_ * K3) return;
    const int o = idx / K3;
    const int c = idx % K3;
    const int k = c / CIN_;
    const int i = c % CIN_;
    g_W2t[idx] = tok_w[(o * CIN_ + i) * 3 + k];
}
__global__ void k_xcat(const float* __restrict__ x, const float* __restrict__ cls,
                       __nv_bfloat16* __restrict__ sOut) {
    const size_t idx = (size_t)blockIdx.x * blockDim.x + threadIdx.x;
    if (idx >= (size_t)BE_ * L_ * K3) return;
    const int c  = (int)(idx % K3);
    const int l  = (int)((idx / K3) % L_);
    const int be = (int)(idx / ((size_t)K3 * L_));
    const int k = c / CIN_;
    const int i = c % CIN_;
    const int ls = (l + k - 1 + L_) % L_;
    const int b  = be / CH_;
    const int ch = be % CH_;
    float v;
    if (ls == 0) v = cls[ch * CIN_ + i];
    else         v = x[(((size_t)b * T_ + (ls - 1)) * CH_ + ch) * CIN_ + i];
    write_split(sOut + (size_t)(be * L_ + l) * 576 + c, K3, v);
}
__global__ void k_posadd(__nv_bfloat16* __restrict__ sOut) {
    const size_t idx = (size_t)blockIdx.x * blockDim.x + threadIdx.x;
    if (idx >= (size_t)BE_ * L_ * D_) return;
    const int d = (int)(idx & 511);
    const int l = (int)((idx >> 9) % L_);
    const int j = d >> 1;
    const float div = expf(-(float)(2 * j) * (9.210340371976184f / (float)D_));
    const float ang = (float)l * div;
    const float v = g_h[idx] + ((d & 1) ? cosf(ang) : sinf(ang));
    g_h[idx] = v;
    write_split(sOut + (idx >> 9) * 1536 + d, 512, v);
}

// ---------------- complex frequency mixing (X2 layout: (be, m, d)) ----------------
__global__ void k_mix2(const float* __restrict__ X2,
                       const float* __restrict__ fwr, const float* __restrict__ fwi,
                       float* __restrict__ Ainv) {
    const int hh = blockIdx.x;
    const int m  = blockIdx.y;
    const int tid = threadIdx.x;
    __shared__ float sWr[64][64];
    __shared__ float sWi[64][64];
    __shared__ float sXr[4][64];
    __shared__ float sXi[4][64];
    for (int idx = tid; idx < 4096; idx += 256) {
        const int i = idx >> 6, o = idx & 63;
        const size_t w = (((size_t)hh * 64 + i) * 64 + o) * 64 + m;
        sWr[i][o] = fwr[w];
        sWi[i][o] = fwi[w];
    }
    __syncthreads();
    const int o    = tid & 63;
    const int bloc = tid >> 6;
    const float cm = ((m == 0) ? 1.f : 2.f) / (float)L_;
    for (int be0 = 0; be0 < BE_; be0 += 4) {
        {
            const int i = tid & 63, bl = tid >> 6;
            const size_t xb = (size_t)(be0 + bl) * 128 * D_ + hh * 64 + i;
            sXr[bl][i] = X2[xb + (size_t)m * D_];
            sXi[bl][i] = X2[xb + (size_t)(64 + m) * D_];
        }
        __syncthreads();
        float ar = 0.f, ai = 0.f;
        #pragma unroll 8
        for (int i = 0; i < 64; ++i) {
            const float xr = sXr[bloc][i], xi = sXi[bloc][i];
            const float wr = sWr[i][o],    wi = sWi[i][o];
            ar += xr * wr - xi * wi;
            ai += xr * wi + xi * wr;
        }
        const size_t row = (size_t)(be0 + bloc) * D_ + hh * 64 + o;
        Ainv[row * 128 + m]      = cm * ar;
        Ainv[row * 128 + 64 + m] = cm * ai;
        __syncthreads();
    }
}

// ---------------- series_decomp residual with fused split ----------------
__global__ void k_movmean(float* __restrict__ hbuf, __nv_bfloat16* __restrict__ sOut) {
    const int be = blockIdx.x;
    const int d0 = blockIdx.y * 32;
    __shared__ float s[L_ * 32];
    const int tid = threadIdx.x;
    for (int idx = tid; idx < L_ * 32; idx += 256) {
        const int l = idx >> 5, dd = idx & 31;
        s[idx] = hbuf[((size_t)be * L_ + l) * D_ + d0 + dd];
    }
    __syncthreads();
    for (int idx = tid; idx < L_ * 32; idx += 256) {
        const int l = idx >> 5, dd = idx & 31;
        float acc = 0.f;
        #pragma unroll
        for (int j = -12; j <= 12; ++j) {
            int jj = l + j;
            jj = jj < 0 ? 0 : (jj > L_ - 1 ? L_ - 1 : jj);
            acc += s[(jj << 5) + dd];
        }
        const float v = s[idx] - acc * (1.f / 25.f);
        const size_t row = (size_t)be * L_ + l;
        hbuf[row * D_ + d0 + dd] = v;
        write_split(sOut + row * 1536 + d0 + dd, 512, v);
    }
}

// ---------------- final LayerNorm + mean-pool ----------------
__global__ void k_lnpool(const float* __restrict__ g, const float* __restrict__ b) {
    const int be = blockIdx.x;
    const int tid = threadIdx.x;
    __shared__ float ws[16], ws2[16];
    const int wid = tid >> 5, lane = tid & 31;
    const float gg = g[tid], bb = b[tid];
    float acc = 0.f;
    for (int l = 0; l < L_; ++l) {
        const float v = g_h[((size_t)be * L_ + l) * D_ + tid];
        float s = v, s2 = v * v;
        #pragma unroll
        for (int off = 16; off > 0; off >>= 1) {
            s  += __shfl_xor_sync(0xffffffffu, s, off);
            s2 += __shfl_xor_sync(0xffffffffu, s2, off);
        }
        if (lane == 0) { ws[wid] = s; ws2[wid] = s2; }
        __syncthreads();
        float tot = 0.f, tot2 = 0.f;
        #pragma unroll
        for (int w = 0; w < 16; ++w) { tot += ws[w]; tot2 += ws2[w]; }
        const float mu  = tot * (1.f / (float)D_);
        const float var = tot2 * (1.f / (float)D_) - mu * mu;
        const float inv = rsqrtf(var + 1e-5f);
        acc += (v - mu) * inv * gg + bb;
        __syncthreads();
    }
    g_z[(size_t)be * D_ + tid] = acc * (1.f / (float)L_);
}

// ---------------- decoders ----------------
__global__ void k_dec1(const float* __restrict__ w, const float* __restrict__ b1) {
    const int tid = threadIdx.x;
    const int warp = tid >> 5, lane = tid & 31;
    const int idx = blockIdx.x * 8 + warp;
    const int bb = idx >> 9;
    const int oo = idx & 511;
    const float* zr = g_z + (size_t)bb * (CH_ * D_);
    const float* wr = w   + (size_t)oo * (CH_ * D_);
    float acc = 0.f;
    for (int k = lane * 4; k < CH_ * D_; k += 128) {
        const float4 zv = *reinterpret_cast<const float4*>(zr + k);
        const float4 wv = *reinterpret_cast<const float4*>(wr + k);
        acc += zv.x * wv.x + zv.y * wv.y + zv.z * wv.z + zv.w * wv.w;
    }
    #pragma unroll
    for (int off = 16; off > 0; off >>= 1) acc += __shfl_xor_sync(0xffffffffu, acc, off);
    if (lane == 0) {
        const float v = acc + b1[oo];
        g_z2[idx] = gelu1(v);
    }
}
__global__ void k_dec2(const float* __restrict__ w, const float* __restrict__ bias,
                       float* __restrict__ out) {
    const int bb = blockIdx.x;
    const int tid = threadIdx.x;
    float acc = 0.f;
    for (int d = tid; d < D_; d += 128) acc += g_z2[bb * D_ + d] * w[d];
    #pragma unroll
    for (int off = 16; off > 0; off >>= 1) acc += __shfl_xor_sync(0xffffffffu, acc, off);
    __shared__ float ws[4];
    if ((tid & 31) == 0) ws[tid >> 5] = acc;
    __syncthreads();
    if (tid == 0) out[bb] = ws[0] + ws[1] + ws[2] + ws[3] + bias[0];
}

// ---------------- orchestration ----------------
extern "C" void kernel_launch(void* const* d_in, const int* in_sizes, int n_in,
                              void* d_out, int out_size) {
    const float* x     = (const float*)d_in[0];
    const float* cls   = (const float*)d_in[3];
    const float* tok_w = (const float*)d_in[4];
    const float* wq    = (const float*)d_in[5];
    const float* bq    = (const float*)d_in[6];
    const float* wo    = (const float*)d_in[7];
    const float* bo    = (const float*)d_in[8];
    const float* c1w   = (const float*)d_in[9];
    const float* c2w   = (const float*)d_in[10];
    const float* fwr   = (const float*)d_in[11];
    const float* fwi   = (const float*)d_in[12];
    const float* ng    = (const float*)d_in[13];
    const float* nb    = (const float*)d_in[14];
    const float* d1w   = (const float*)d_in[15];
    const float* d1b   = (const float*)d_in[16];
    const float* d2w   = (const float*)d_in[17];
    const float* d2b   = (const float*)d_in[18];
    float* out = (float*)d_out;

    float *ph, *pq, *pt, *pxq, *pW2t, *pcs, *pBinv;
    __nv_bfloat16 *pA2a, *pA2b, *pB2;
    cudaGetSymbolAddress((void**)&ph,    g_h);
    cudaGetSymbolAddress((void**)&pq,    g_q);
    cudaGetSymbolAddress((void**)&pt,    g_t);
    cudaGetSymbolAddress((void**)&pxq,   g_xq);
    cudaGetSymbolAddress((void**)&pW2t,  g_W2t);
    cudaGetSymbolAddress((void**)&pcs,   g_cs);
    cudaGetSymbolAddress((void**)&pBinv, g_Binv);
    cudaGetSymbolAddress((void**)&pA2a,  g_A2a);
    cudaGetSymbolAddress((void**)&pA2b,  g_A2b);
    cudaGetSymbolAddress((void**)&pB2,   g_B2);

    // X2 lives in the upper half of g_xq (free until inverse GEMM overwrites it,
    // which happens strictly after k_mix2 has consumed X2).
    float* pX2   = pxq + (size_t)BE_ * 128 * D_;
    float* pAinv = pt;

    cudaFuncSetAttribute(k_mma, cudaFuncAttributeMaxDynamicSharedMemorySize, SMEM_MMA);

    const dim3 gTC(2, MR / 128);            // 128x256 CTA tiles
    const dim3 gDft(4, 1, BE_);             // batched DFT NN-gemm
    const dim3 gemmInv(2, R_ / 128);
    const int splitAblk  = (MR * D_ / 4 + 255) / 256;
    const int splitWblk  = (D_ * D_ / 4 + 255) / 256;
    const int splitW3blk = (D_ * K3 / 4 + 255) / 256;

    // tables
    k_init_cs  <<<(128 * LP_ + 255) / 256, 256>>>();
    k_init_binv<<<(L_ * 2 * M_ + 255) / 256, 256>>>();

    // embedding
    k_w2t <<<(D_ * K3 + 255) / 256, 256>>>(tok_w);
    k_xcat<<<(int)(((size_t)BE_ * L_ * K3 + 255) / 256), 256>>>(x, cls, pA2a);
    k_splitW<<<splitW3blk, 256>>>(pW2t, pB2, K3, D_ * K3 / 4);
    k_mma<<<gTC, 256, SMEM_MMA>>>(pA2a, pB2, ph, nullptr, nullptr, 3 * K3, 0);
    k_posadd<<<(int)(((size_t)BE_ * L_ * D_ + 255) / 256), 256>>>(pA2a);

    for (int l = 0; l < NL_; ++l) {
        const float* wql = wq + (size_t)l * D_ * D_;
        const float* bql = bq + (size_t)l * D_;
        const float* wol = wo + (size_t)l * D_ * D_;
        const float* bol = bo + (size_t)l * D_;
        const float* c1l = c1w + (size_t)l * D_ * D_;
        const float* c2l = c2w + (size_t)l * D_ * D_;

        // q = h @ wq^T + bq
        k_splitW<<<splitWblk, 256>>>(wql, pB2, D_, D_ * D_ / 4);
        k_mma<<<gTC, 256, SMEM_MMA>>>(pA2a, pB2, pq, bql, nullptr, 3 * D_, 0);
        // batched DFT (no transpose): X2[be] = cs @ q[be]
        k_dftb<<<gDft, 256>>>(pcs, pq, pX2);
        // mix -> Ainv
        k_mix2<<<dim3(H_, M_), 256>>>(pX2, fwr, fwi, pAinv);
        // inverse DFT -> fp32 xq (raw reshape to (MR,512)); last col separate
        k_gemm128<<<gemmInv, 256>>>(pAinv, pBinv, pxq, 257, 2 * M_);
        k_lastcol<<<R_ / 256, 256>>>(pAinv, pBinv, pxq);
        k_split<<<splitAblk, 256>>>(pxq, pA2b, D_, MR * D_ / 4);
        // h = h + a @ wo^T + bo
        k_splitW<<<splitWblk, 256>>>(wol, pB2, D_, D_ * D_ / 4);
        k_mma<<<gTC, 256, SMEM_MMA>>>(pA2b, pB2, ph, bol, ph, 3 * D_, 1);
        k_movmean<<<dim3(BE_, D_ / 32), 256>>>(ph, pA2a);
        // FFN: conv1 gelu -> fp32 t; split t -> A2b (R11-proven path)
        k_splitW<<<splitWblk, 256>>>(c1l, pB2, D_, D_ * D_ / 4);
        k_mma<<<gTC, 256, SMEM_MMA>>>(pA2a, pB2, pt, nullptr, nullptr, 3 * D_, 2);
        k_split<<<splitAblk, 256>>>(pt, pA2b, D_, MR * D_ / 4);
        k_splitW<<<splitWblk, 256>>>(c2l, pB2, D_, D_ * D_ / 4);
        k_mma<<<gTC, 256, SMEM_MMA>>>(pA2b, pB2, ph, nullptr, ph, 3 * D_, 1);
        k_movmean<<<dim3(BE_, D_ / 32), 256>>>(ph, pA2a);
    }

    k_lnpool<<<BE_, 512>>>(ng, nb);
    k_dec1<<<B_ * D_ / 8, 256>>>(d1w, d1b);
    k_dec2<<<B_, 128>>>(d2w, d2b, out);
}

// round 17
// speedup vs baseline: 1.1474x; 1.0089x over previous
#include <cuda_runtime.h>
#include <cuda_bf16.h>
#include <math.h>
#include <stdint.h>

// ---------------- problem constants ----------------
constexpr int B_   = 16;
constexpr int T_   = 256;
constexpr int CH_  = 16;
constexpr int CIN_ = 64;
constexpr int D_   = 512;
constexpr int H_   = 8;
constexpr int E_   = 64;
constexpr int NL_  = 2;
constexpr int M_   = 64;
constexpr int L_   = T_ + 1; // 257
constexpr int LP_  = 264;
constexpr int BE_  = B_ * CH_;      // 256
constexpr int MR   = BE_ * L_;      // 65792 = 514*128
constexpr int R_   = BE_ * D_;      // 131072
constexpr int K3   = 3 * CIN_;      // 192

// ---------------- scratch ----------------
__device__ float g_h   [(size_t)BE_ * L_ * D_];
__device__ float g_q   [(size_t)BE_ * L_ * D_];
__device__ float g_t   [(size_t)BE_ * L_ * D_];   // Ainv alias + conv1 fp32 out
__device__ float g_xq  [(size_t)BE_ * D_ * L_];   // inverse output; 2nd half holds X2
__device__ float g_W2t [(size_t)D_ * K3];
__device__ float g_cs  [128 * LP_];               // cs[m, l], zero-padded l>=257
__device__ float g_Binv[L_ * 2 * M_];
__device__ float g_z  [BE_ * D_];
__device__ float g_z2 [B_ * D_];
__device__ __nv_bfloat16 g_A2a[(size_t)MR * 3 * D_];  // split activations (ping)
__device__ __nv_bfloat16 g_A2b[(size_t)MR * 3 * D_];  // split activations (pong)
__device__ __nv_bfloat16 g_B2 [(size_t)D_ * 3 * D_];  // split weights [hi|hi|lo]
__device__ __nv_bfloat16 g_B2i[(size_t)L_ * 3 * 128]; // split Binv [hi|hi|lo]

// ================= helpers =================
__device__ __forceinline__ uint32_t smem_u32(const void* p) {
    uint32_t a;
    asm("{ .reg .u64 t; cvta.to.shared.u64 t, %1; cvt.u32.u64 %0, t; }" : "=r"(a) : "l"(p));
    return a;
}
__device__ __forceinline__ void ldsm4(uint32_t& r0, uint32_t& r1, uint32_t& r2, uint32_t& r3,
                                      uint32_t a) {
    asm volatile("ldmatrix.sync.aligned.m8n8.x4.shared.b16 {%0,%1,%2,%3}, [%4];"
                 : "=r"(r0), "=r"(r1), "=r"(r2), "=r"(r3) : "r"(a));
}
__device__ __forceinline__ void mma_bf16(float& d0, float& d1, float& d2, float& d3,
                                         uint32_t a0, uint32_t a1, uint32_t a2, uint32_t a3,
                                         uint32_t b0, uint32_t b1) {
    asm volatile("mma.sync.aligned.m16n8k16.row.col.f32.bf16.bf16.f32 "
                 "{%0,%1,%2,%3}, {%4,%5,%6,%7}, {%8,%9}, {%0,%1,%2,%3};"
                 : "+f"(d0), "+f"(d1), "+f"(d2), "+f"(d3)
                 : "r"(a0), "r"(a1), "r"(a2), "r"(a3), "r"(b0), "r"(b1));
}
__device__ __forceinline__ void cp16(uint32_t dst, const void* src) {
    asm volatile("cp.async.cg.shared.global [%0], [%1], 16;"
                 :: "r"(dst), "l"(__cvta_generic_to_global(src)) : "memory");
}
// A-side split layout [hi | lo | hi]
__device__ __forceinline__ void write_split(__nv_bfloat16* o, int K, float v) {
    const __nv_bfloat16 hi = __float2bfloat16_rn(v);
    const __nv_bfloat16 lo = __float2bfloat16_rn(v - __bfloat162float(hi));
    o[0] = hi; o[K] = lo; o[2 * K] = hi;
}
__device__ __forceinline__ float gelu1(float v) {
    return 0.5f * v * (1.f + erff(v * 0.70710678118654752f));
}

// ========== standalone A-split: fp32 [rows,K] -> bf16 [rows,3K] = [hi|lo|hi] ==========
__global__ void k_split(const float* __restrict__ A, __nv_bfloat16* __restrict__ out,
                        int K, int total4) {
    const int idx = blockIdx.x * blockDim.x + threadIdx.x;
    if (idx >= total4) return;
    const int Kq = K >> 2;
    const int row = idx / Kq;
    const int c   = (idx - row * Kq) << 2;
    const float4 v = *reinterpret_cast<const float4*>(A + (size_t)row * K + c);
    __nv_bfloat16 hi[4], lo[4];
    const float vv[4] = {v.x, v.y, v.z, v.w};
    #pragma unroll
    for (int j = 0; j < 4; ++j) {
        hi[j] = __float2bfloat16_rn(vv[j]);
        lo[j] = __float2bfloat16_rn(vv[j] - __bfloat162float(hi[j]));
    }
    __nv_bfloat16* o = out + (size_t)row * (3 * K);
    const uint2 hv = *reinterpret_cast<uint2*>(hi);
    const uint2 lv = *reinterpret_cast<uint2*>(lo);
    *reinterpret_cast<uint2*>(o + c)         = hv;
    *reinterpret_cast<uint2*>(o + K + c)     = lv;
    *reinterpret_cast<uint2*>(o + 2 * K + c) = hv;
}

// ========== weight split: [hi|hi|lo] ==========
__global__ void k_splitW(const float* __restrict__ A, __nv_bfloat16* __restrict__ out,
                         int K, int total4) {
    const int idx = blockIdx.x * blockDim.x + threadIdx.x;
    if (idx >= total4) return;
    const int Kq = K >> 2;
    const int row = idx / Kq;
    const int c   = (idx - row * Kq) << 2;
    const float4 v = *reinterpret_cast<const float4*>(A + (size_t)row * K + c);
    __nv_bfloat16 hi[4], lo[4];
    const float vv[4] = {v.x, v.y, v.z, v.w};
    #pragma unroll
    for (int j = 0; j < 4; ++j) {
        hi[j] = __float2bfloat16_rn(vv[j]);
        lo[j] = __float2bfloat16_rn(vv[j] - __bfloat162float(hi[j]));
    }
    __nv_bfloat16* o = out + (size_t)row * (3 * K);
    const uint2 hv = *reinterpret_cast<uint2*>(hi);
    const uint2 lv = *reinterpret_cast<uint2*>(lo);
    *reinterpret_cast<uint2*>(o + c)         = hv;
    *reinterpret_cast<uint2*>(o + K + c)     = hv;
    *reinterpret_cast<uint2*>(o + 2 * K + c) = lv;
}

// ================= bf16 mma.sync GEMM: C[M, grid.x*256] = A2 @ B2^T =============
// CTA tile 128x256, 8 warps, warp tile 64x64, 2-stage cp.async (110,592 B).
// mode 0: +bias ; 1: +bias+res ; 2: gelu(+bias).  C row stride = Cstride
// (odd stride -> scalar stores).  All computed columns must be valid.
constexpr int STAGE_BYTES = 384 * 144;
constexpr int SMEM_MMA    = 2 * STAGE_BYTES;     // 110592

__global__ __launch_bounds__(256, 1)
void k_mma(const __nv_bfloat16* __restrict__ A2, const __nv_bfloat16* __restrict__ B2,
           float* __restrict__ C, const float* __restrict__ bias,
           const float* __restrict__ res, int K2, int mode, int Cstride) {
    extern __shared__ char smem[];
    const uint32_t sb = smem_u32(smem);
    const int tid = threadIdx.x;
    const int wid = tid >> 5, lane = tid & 31;
    const int mw = (wid & 1) * 64;
    const int nw = (wid >> 1) * 64;
    const int m0 = blockIdx.y * 128;
    const int n0 = blockIdx.x * 256;

    float acc[4][8][4] = {};
    const int nch = K2 >> 6;

    #define LOAD_STAGE(c, s) do {                                                   \
        const uint32_t base = sb + (s) * STAGE_BYTES;                               \
        _Pragma("unroll")                                                           \
        for (int i = 0; i < 12; ++i) {                                              \
            const int idx = i * 256 + tid;                                          \
            const int r = idx >> 3, sg = idx & 7;                                   \
            const __nv_bfloat16* src = (r < 128)                                    \
                ? A2 + (size_t)(m0 + r) * K2 + (c) * 64 + sg * 8                    \
                : B2 + (size_t)(n0 + r - 128) * K2 + (c) * 64 + sg * 8;             \
            cp16(base + r * 144 + sg * 16, src);                                    \
        }                                                                           \
        asm volatile("cp.async.commit_group;" ::: "memory");                        \
    } while (0)

    LOAD_STAGE(0, 0);

    const int a_row = mw + (lane & 15);
    const int a_kof = (lane >> 4) * 8;
    const int b_row = nw + ((lane >> 4) << 3) + (lane & 7);
    const int b_kof = ((lane >> 3) & 1) * 8;

    for (int c = 0; c < nch; ++c) {
        asm volatile("cp.async.wait_group 0;" ::: "memory");
        __syncthreads();
        if (c + 1 < nch) LOAD_STAGE(c + 1, (c + 1) & 1);

        const uint32_t aB = sb + (c & 1) * STAGE_BYTES;
        const uint32_t bB = aB + 128 * 144;

        #pragma unroll
        for (int ks = 0; ks < 4; ++ks) {
            uint32_t a[4][4];
            #pragma unroll
            for (int mt = 0; mt < 4; ++mt)
                ldsm4(a[mt][0], a[mt][1], a[mt][2], a[mt][3],
                      aB + (a_row + mt * 16) * 144 + (ks * 16 + a_kof) * 2);
            uint32_t b[8][2];
            #pragma unroll
            for (int np = 0; np < 4; ++np)
                ldsm4(b[np * 2][0], b[np * 2][1], b[np * 2 + 1][0], b[np * 2 + 1][1],
                      bB + (b_row + np * 16) * 144 + (ks * 16 + b_kof) * 2);
            #pragma unroll
            for (int mt = 0; mt < 4; ++mt)
                #pragma unroll
                for (int nt = 0; nt < 8; ++nt)
                    mma_bf16(acc[mt][nt][0], acc[mt][nt][1], acc[mt][nt][2], acc[mt][nt][3],
                             a[mt][0], a[mt][1], a[mt][2], a[mt][3],
                             b[nt][0], b[nt][1]);
        }
    }
    #undef LOAD_STAGE

    #pragma unroll
    for (int mt = 0; mt < 4; ++mt) {
        #pragma unroll
        for (int half = 0; half < 2; ++half) {
            const int m = m0 + mw + mt * 16 + (lane >> 2) + half * 8;
            float* Crow = C + (size_t)m * Cstride;
            const float* Rrow = (mode == 1) ? res + (size_t)m * Cstride : nullptr;
            #pragma unroll
            for (int nt = 0; nt < 8; ++nt) {
                const int n = n0 + nw + nt * 8 + (lane & 3) * 2;
                float v0 = acc[mt][nt][half * 2 + 0];
                float v1 = acc[mt][nt][half * 2 + 1];
                if (bias) { v0 += bias[n]; v1 += bias[n + 1]; }
                if (mode == 1) { v0 += Rrow[n]; v1 += Rrow[n + 1]; }
                else if (mode == 2) { v0 = gelu1(v0); v1 = gelu1(v1); }
                if (Cstride & 1) {
                    Crow[n] = v0; Crow[n + 1] = v1;
                } else {
                    float2 o; o.x = v0; o.y = v1;
                    *reinterpret_cast<float2*>(Crow + n) = o;
                }
            }
        }
    }
}

// ============ batched DFT NN-GEMM: X2[be](128x512) = cs(128xL) @ q[be](Lx512) ==========
__global__ __launch_bounds__(256, 2)
void k_dftb(const float* __restrict__ cs, const float* __restrict__ q,
            float* __restrict__ X2) {
    __shared__ float sA[2][8][128];
    __shared__ float sB[2][8][128];
    const int tid = threadIdx.x;
    const int be = blockIdx.z;
    const int n0 = blockIdx.x * 128;
    const float* qb = q + (size_t)be * L_ * D_;
    float* Xb = X2 + (size_t)be * 128 * D_;

    const int lrow = tid >> 1;
    const int lcol = (tid & 1) * 4;
    const int bkk = tid >> 5;
    const int bn  = (tid & 31) * 4;
    const int tx = tid & 15, ty = tid >> 4;

    float acc[8][8] = {};
    {
        const float4 a = *reinterpret_cast<const float4*>(cs + (size_t)lrow * LP_ + lcol);
        sA[0][lcol + 0][lrow] = a.x; sA[0][lcol + 1][lrow] = a.y;
        sA[0][lcol + 2][lrow] = a.z; sA[0][lcol + 3][lrow] = a.w;
        float4 b = make_float4(0.f, 0.f, 0.f, 0.f);
        if (bkk < L_) b = *reinterpret_cast<const float4*>(qb + (size_t)bkk * D_ + n0 + bn);
        *reinterpret_cast<float4*>(&sB[0][bkk][bn]) = b;
    }
    __syncthreads();
    const int nstages = LP_ >> 3;   // 33
    int buf = 0;
    #define DFT_STAGE(BUF)                                                          \
        _Pragma("unroll")                                                           \
        for (int k = 0; k < 8; ++k) {                                               \
            const float4 a0 = *reinterpret_cast<const float4*>(&sA[BUF][k][ty * 4]);       \
            const float4 a1 = *reinterpret_cast<const float4*>(&sA[BUF][k][64 + ty * 4]);  \
            const float4 b0 = *reinterpret_cast<const float4*>(&sB[BUF][k][tx * 4]);       \
            const float4 b1 = *reinterpret_cast<const float4*>(&sB[BUF][k][64 + tx * 4]);  \
            const float av[8] = {a0.x, a0.y, a0.z, a0.w, a1.x, a1.y, a1.z, a1.w};   \
            const float bv[8] = {b0.x, b0.y, b0.z, b0.w, b1.x, b1.y, b1.z, b1.w};   \
            _Pragma("unroll")                                                       \
            for (int i = 0; i < 8; ++i)                                             \
                _Pragma("unroll")                                                   \
                for (int j = 0; j < 8; ++j)                                         \
                    acc[i][j] += av[i] * bv[j];                                     \
        }
    for (int s = 1; s < nstages; ++s) {
        const int k0 = s * 8;
        const float4 a = *reinterpret_cast<const float4*>(cs + (size_t)lrow * LP_ + k0 + lcol);
        float4 b = make_float4(0.f, 0.f, 0.f, 0.f);
        if (k0 + bkk < L_) b = *reinterpret_cast<const float4*>(qb + (size_t)(k0 + bkk) * D_ + n0 + bn);
        DFT_STAGE(buf)
        const int nb = buf ^ 1;
        sA[nb][lcol + 0][lrow] = a.x; sA[nb][lcol + 1][lrow] = a.y;
        sA[nb][lcol + 2][lrow] = a.z; sA[nb][lcol + 3][lrow] = a.w;
        *reinterpret_cast<float4*>(&sB[nb][bkk][bn]) = b;
        __syncthreads();
        buf = nb;
    }
    DFT_STAGE(buf)
    #undef DFT_STAGE

    #pragma unroll
    for (int i = 0; i < 8; ++i) {
        const int m = (i < 4) ? (ty * 4 + i) : (64 + ty * 4 + i - 4);
        float* Crow = Xb + (size_t)m * D_;
        #pragma unroll
        for (int j = 0; j < 8; ++j) {
            const int n = n0 + ((j < 4) ? (tx * 4 + j) : (64 + tx * 4 + j - 4));
            Crow[n] = acc[i][j];
        }
    }
}

// last column (l=256) of inverse DFT -> fp32 xq
__global__ void k_lastcol(const float* __restrict__ Ainv, const float* __restrict__ Binv,
                          float* __restrict__ xq) {
    __shared__ float sb[128];
    const int tid = threadIdx.x;
    if (tid < 128) sb[tid] = Binv[256 * 128 + tid];
    __syncthreads();
    const int r = blockIdx.x * 256 + tid;
    const float* ar = Ainv + (size_t)r * 128;
    float acc = 0.f;
    #pragma unroll 8
    for (int k = 0; k < 128; ++k) acc += ar[k] * sb[k];
    xq[(size_t)r * 257 + 256] = acc;
}

// ---------------- DFT basis tables ----------------
__global__ void k_init_cs() {
    const int idx = blockIdx.x * blockDim.x + threadIdx.x;
    if (idx >= 128 * LP_) return;
    const int n = idx / LP_;
    const int l = idx % LP_;
    float v = 0.f;
    if (l < L_) {
        const int m = (n < M_) ? n : (n - M_);
        const long r = ((long)m * l) % L_;
        const double ang = 6.283185307179586476925 * (double)r / (double)L_;
        v = (n < M_) ? (float)cos(ang) : (float)(-sin(ang));
    }
    g_cs[idx] = v;
}
__global__ void k_init_binv() {
    const int idx = blockIdx.x * blockDim.x + threadIdx.x;
    if (idx >= L_ * 2 * M_) return;
    const int t = idx / (2 * M_);
    const int k = idx % (2 * M_);
    const int m = (k < M_) ? k : (k - M_);
    const long r = ((long)t * m) % L_;
    const double ang = 6.283185307179586476925 * (double)r / (double)L_;
    g_Binv[idx] = (k < M_) ? (float)cos(ang) : (float)(-sin(ang));
}

// ---------------- token embedding prep ----------------
__global__ void k_w2t(const float* __restrict__ tok_w) {
    const int idx = blockIdx.x * blockDim.x + threadIdx.x;
    if (idx >= D_ * K3) return;
    const int o = idx / K3;
    const int c = idx % K3;
    const int k = c / CIN_;
    const int i = c % CIN_;
    g_W2t[idx] = tok_w[(o * CIN_ + i) * 3 + k];
}
__global__ void k_xcat(const float* __restrict__ x, const float* __restrict__ cls,
                       __nv_bfloat16* __restrict__ sOut) {
    const size_t idx = (size_t)blockIdx.x * blockDim.x + threadIdx.x;
    if (idx >= (size_t)BE_ * L_ * K3) return;
    const int c  = (int)(idx % K3);
    const int l  = (int)((idx / K3) % L_);
    const int be = (int)(idx / ((size_t)K3 * L_));
    const int k = c / CIN_;
    const int i = c % CIN_;
    const int ls = (l + k - 1 + L_) % L_;
    const int b  = be / CH_;
    const int ch = be % CH_;
    float v;
    if (ls == 0) v = cls[ch * CIN_ + i];
    else         v = x[(((size_t)b * T_ + (ls - 1)) * CH_ + ch) * CIN_ + i];
    write_split(sOut + (size_t)(be * L_ + l) * 576 + c, K3, v);
}
__global__ void k_posadd(__nv_bfloat16* __restrict__ sOut) {
    const size_t idx = (size_t)blockIdx.x * blockDim.x + threadIdx.x;
    if (idx >= (size_t)BE_ * L_ * D_) return;
    const int d = (int)(idx & 511);
    const int l = (int)((idx >> 9) % L_);
    const int j = d >> 1;
    const float div = expf(-(float)(2 * j) * (9.210340371976184f / (float)D_));
    const float ang = (float)l * div;
    const float v = g_h[idx] + ((d & 1) ? cosf(ang) : sinf(ang));
    g_h[idx] = v;
    write_split(sOut + (idx >> 9) * 1536 + d, 512, v);
}

// ---------------- complex frequency mixing (X2 layout: (be, m, d)) ----------------
__global__ void k_mix2(const float* __restrict__ X2,
                       const float* __restrict__ fwr, const float* __restrict__ fwi,
                       float* __restrict__ Ainv) {
    const int hh = blockIdx.x;
    const int m  = blockIdx.y;
    const int tid = threadIdx.x;
    __shared__ float sWr[64][64];
    __shared__ float sWi[64][64];
    __shared__ float sXr[4][64];
    __shared__ float sXi[4][64];
    for (int idx = tid; idx < 4096; idx += 256) {
        const int i = idx >> 6, o = idx & 63;
        const size_t w = (((size_t)hh * 64 + i) * 64 + o) * 64 + m;
        sWr[i][o] = fwr[w];
        sWi[i][o] = fwi[w];
    }
    __syncthreads();
    const int o    = tid & 63;
    const int bloc = tid >> 6;
    const float cm = ((m == 0) ? 1.f : 2.f) / (float)L_;
    for (int be0 = 0; be0 < BE_; be0 += 4) {
        {
            const int i = tid & 63, bl = tid >> 6;
            const size_t xb = (size_t)(be0 + bl) * 128 * D_ + hh * 64 + i;
            sXr[bl][i] = X2[xb + (size_t)m * D_];
            sXi[bl][i] = X2[xb + (size_t)(64 + m) * D_];
        }
        __syncthreads();
        float ar = 0.f, ai = 0.f;
        #pragma unroll 8
        for (int i = 0; i < 64; ++i) {
            const float xr = sXr[bloc][i], xi = sXi[bloc][i];
            const float wr = sWr[i][o],    wi = sWi[i][o];
            ar += xr * wr - xi * wi;
            ai += xr * wi + xi * wr;
        }
        const size_t row = (size_t)(be0 + bloc) * D_ + hh * 64 + o;
        Ainv[row * 128 + m]      = cm * ar;
        Ainv[row * 128 + 64 + m] = cm * ai;
        __syncthreads();
    }
}

// ---------------- series_decomp residual with fused split ----------------
__global__ void k_movmean(float* __restrict__ hbuf, __nv_bfloat16* __restrict__ sOut) {
    const int be = blockIdx.x;
    const int d0 = blockIdx.y * 32;
    __shared__ float s[L_ * 32];
    const int tid = threadIdx.x;
    for (int idx = tid; idx < L_ * 32; idx += 256) {
        const int l = idx >> 5, dd = idx & 31;
        s[idx] = hbuf[((size_t)be * L_ + l) * D_ + d0 + dd];
    }
    __syncthreads();
    for (int idx = tid; idx < L_ * 32; idx += 256) {
        const int l = idx >> 5, dd = idx & 31;
        float acc = 0.f;
        #pragma unroll
        for (int j = -12; j <= 12; ++j) {
            int jj = l + j;
            jj = jj < 0 ? 0 : (jj > L_ - 1 ? L_ - 1 : jj);
            acc += s[(jj << 5) + dd];
        }
        const float v = s[idx] - acc * (1.f / 25.f);
        const size_t row = (size_t)be * L_ + l;
        hbuf[row * D_ + d0 + dd] = v;
        write_split(sOut + row * 1536 + d0 + dd, 512, v);
    }
}

// ---------------- final LayerNorm + mean-pool ----------------
__global__ void k_lnpool(const float* __restrict__ g, const float* __restrict__ b) {
    const int be = blockIdx.x;
    const int tid = threadIdx.x;
    __shared__ float ws[16], ws2[16];
    const int wid = tid >> 5, lane = tid & 31;
    const float gg = g[tid], bb = b[tid];
    float acc = 0.f;
    for (int l = 0; l < L_; ++l) {
        const float v = g_h[((size_t)be * L_ + l) * D_ + tid];
        float s = v, s2 = v * v;
        #pragma unroll
        for (int off = 16; off > 0; off >>= 1) {
            s  += __shfl_xor_sync(0xffffffffu, s, off);
            s2 += __shfl_xor_sync(0xffffffffu, s2, off);
        }
        if (lane == 0) { ws[wid] = s; ws2[wid] = s2; }
        __syncthreads();
        float tot = 0.f, tot2 = 0.f;
        #pragma unroll
        for (int w = 0; w < 16; ++w) { tot += ws[w]; tot2 += ws2[w]; }
        const float mu  = tot * (1.f / (float)D_);
        const float var = tot2 * (1.f / (float)D_) - mu * mu;
        const float inv = rsqrtf(var + 1e-5f);
        acc += (v - mu) * inv * gg + bb;
        __syncthreads();
    }
    g_z[(size_t)be * D_ + tid] = acc * (1.f / (float)L_);
}

// ---------------- decoders ----------------
__global__ void k_dec1(const float* __restrict__ w, const float* __restrict__ b1) {
    const int tid = threadIdx.x;
    const int warp = tid >> 5, lane = tid & 31;
    const int idx = blockIdx.x * 8 + warp;
    const int bb = idx >> 9;
    const int oo = idx & 511;
    const float* zr = g_z + (size_t)bb * (CH_ * D_);
    const float* wr = w   + (size_t)oo * (CH_ * D_);
    float acc = 0.f;
    for (int k = lane * 4; k < CH_ * D_; k += 128) {
        const float4 zv = *reinterpret_cast<const float4*>(zr + k);
        const float4 wv = *reinterpret_cast<const float4*>(wr + k);
        acc += zv.x * wv.x + zv.y * wv.y + zv.z * wv.z + zv.w * wv.w;
    }
    #pragma unroll
    for (int off = 16; off > 0; off >>= 1) acc += __shfl_xor_sync(0xffffffffu, acc, off);
    if (lane == 0) {
        const float v = acc + b1[oo];
        g_z2[idx] = gelu1(v);
    }
}
__global__ void k_dec2(const float* __restrict__ w, const float* __restrict__ bias,
                       float* __restrict__ out) {
    const int bb = blockIdx.x;
    const int tid = threadIdx.x;
    float acc = 0.f;
    for (int d = tid; d < D_; d += 128) acc += g_z2[bb * D_ + d] * w[d];
    #pragma unroll
    for (int off = 16; off > 0; off >>= 1) acc += __shfl_xor_sync(0xffffffffu, acc, off);
    __shared__ float ws[4];
    if ((tid & 31) == 0) ws[tid >> 5] = acc;
    __syncthreads();
    if (tid == 0) out[bb] = ws[0] + ws[1] + ws[2] + ws[3] + bias[0];
}

// ---------------- orchestration ----------------
extern "C" void kernel_launch(void* const* d_in, const int* in_sizes, int n_in,
                              void* d_out, int out_size) {
    const float* x     = (const float*)d_in[0];
    const float* cls   = (const float*)d_in[3];
    const float* tok_w = (const float*)d_in[4];
    const float* wq    = (const float*)d_in[5];
    const float* bq    = (const float*)d_in[6];
    const float* wo    = (const float*)d_in[7];
    const float* bo    = (const float*)d_in[8];
    const float* c1w   = (const float*)d_in[9];
    const float* c2w   = (const float*)d_in[10];
    const float* fwr   = (const float*)d_in[11];
    const float* fwi   = (const float*)d_in[12];
    const float* ng    = (const float*)d_in[13];
    const float* nb    = (const float*)d_in[14];
    const float* d1w   = (const float*)d_in[15];
    const float* d1b   = (const float*)d_in[16];
    const float* d2w   = (const float*)d_in[17];
    const float* d2b   = (const float*)d_in[18];
    float* out = (float*)d_out;

    float *ph, *pq, *pt, *pxq, *pW2t, *pcs, *pBinv;
    __nv_bfloat16 *pA2a, *pA2b, *pB2, *pB2i;
    cudaGetSymbolAddress((void**)&ph,    g_h);
    cudaGetSymbolAddress((void**)&pq,    g_q);
    cudaGetSymbolAddress((void**)&pt,    g_t);
    cudaGetSymbolAddress((void**)&pxq,   g_xq);
    cudaGetSymbolAddress((void**)&pW2t,  g_W2t);
    cudaGetSymbolAddress((void**)&pcs,   g_cs);
    cudaGetSymbolAddress((void**)&pBinv, g_Binv);
    cudaGetSymbolAddress((void**)&pA2a,  g_A2a);
    cudaGetSymbolAddress((void**)&pA2b,  g_A2b);
    cudaGetSymbolAddress((void**)&pB2,   g_B2);
    cudaGetSymbolAddress((void**)&pB2i,  g_B2i);

    float* pX2   = pxq + (size_t)BE_ * 128 * D_;   // upper half of g_xq
    float* pAinv = pt;

    cudaFuncSetAttribute(k_mma, cudaFuncAttributeMaxDynamicSharedMemorySize, SMEM_MMA);

    const dim3 gTC(2, MR / 128);            // big GEMMs: 128x256 CTA tiles
    const dim3 gInv(1, R_ / 128);           // inverse DFT: cols 0..255
    const dim3 gDft(4, 1, BE_);             // batched DFT NN-gemm
    const int splitAblk  = (MR * D_ / 4 + 255) / 256;
    const int splitWblk  = (D_ * D_ / 4 + 255) / 256;
    const int splitW3blk = (D_ * K3 / 4 + 255) / 256;

    // embedding first
    k_w2t <<<(D_ * K3 + 255) / 256, 256>>>(tok_w);
    k_xcat<<<(int)(((size_t)BE_ * L_ * K3 + 255) / 256), 256>>>(x, cls, pA2a);
    k_splitW<<<splitW3blk, 256>>>(pW2t, pB2, K3, D_ * K3 / 4);
    k_mma<<<gTC, 256, SMEM_MMA>>>(pA2a, pB2, ph, nullptr, nullptr, 3 * K3, 0, 512);
    k_posadd<<<(int)(((size_t)BE_ * L_ * D_ + 255) / 256), 256>>>(pA2a);

    // tables + Binv split (once; needed from first DFT below)
    k_init_cs  <<<(128 * LP_ + 255) / 256, 256>>>();
    k_init_binv<<<(L_ * 2 * M_ + 255) / 256, 256>>>();
    k_splitW<<<(L_ * 128 / 4 + 255) / 256, 256>>>(pBinv, pB2i, 128, L_ * 128 / 4);

    for (int l = 0; l < NL_; ++l) {
        const float* wql = wq + (size_t)l * D_ * D_;
        const float* bql = bq + (size_t)l * D_;
        const float* wol = wo + (size_t)l * D_ * D_;
        const float* bol = bo + (size_t)l * D_;
        const float* c1l = c1w + (size_t)l * D_ * D_;
        const float* c2l = c2w + (size_t)l * D_ * D_;

        // q = h @ wq^T + bq
        k_splitW<<<splitWblk, 256>>>(wql, pB2, D_, D_ * D_ / 4);
        k_mma<<<gTC, 256, SMEM_MMA>>>(pA2a, pB2, pq, bql, nullptr, 3 * D_, 0, 512);
        // batched DFT (no transpose): X2[be] = cs @ q[be]
        k_dftb<<<gDft, 256>>>(pcs, pq, pX2);
        // mix -> Ainv
        k_mix2<<<dim3(H_, M_), 256>>>(pX2, fwr, fwi, pAinv);
        // inverse DFT on tensor cores: split Ainv -> A2b; xq cols 0..255 via mma
        k_split<<<(R_ * 128 / 4 + 255) / 256, 256>>>(pAinv, pA2b, 128, R_ * 128 / 4);
        k_mma<<<gInv, 256, SMEM_MMA>>>(pA2b, pB2i, pxq, nullptr, nullptr, 384, 0, 257);
        k_lastcol<<<R_ / 256, 256>>>(pAinv, pBinv, pxq);
        // split xq (raw reshape to (MR,512)) -> A2b
        k_split<<<splitAblk, 256>>>(pxq, pA2b, D_, MR * D_ / 4);
        // h = h + a @ wo^T + bo
        k_splitW<<<splitWblk, 256>>>(wol, pB2, D_, D_ * D_ / 4);
        k_mma<<<gTC, 256, SMEM_MMA>>>(pA2b, pB2, ph, bol, ph, 3 * D_, 1, 512);
        k_movmean<<<dim3(BE_, D_ / 32), 256>>>(ph, pA2a);
        // FFN: conv1 gelu -> fp32 t; split t -> A2b
        k_splitW<<<splitWblk, 256>>>(c1l, pB2, D_, D_ * D_ / 4);
        k_mma<<<gTC, 256, SMEM_MMA>>>(pA2a, pB2, pt, nullptr, nullptr, 3 * D_, 2, 512);
        k_split<<<splitAblk, 256>>>(pt, pA2b, D_, MR * D_ / 4);
        k_splitW<<<splitWblk, 256>>>(c2l, pB2, D_, D_ * D_ / 4);
        k_mma<<<gTC, 256, SMEM_MMA>>>(pA2b, pB2, ph, nullptr, ph, 3 * D_, 1, 512);
        k_movmean<<<dim3(BE_, D_ / 32), 256>>>(ph, pA2a);
    }

    k_lnpool<<<BE_, 512>>>(ng, nb);
    k_dec1<<<B_ * D_ / 8, 256>>>(d1w, d1b);
    k_dec2<<<B_, 128>>>(d2w, d2b, out);
}